// round 1
// baseline (speedup 1.0000x reference)
#include <cuda_runtime.h>
#include <math.h>

#define B_ROWS 4096
#define D_INF  192
#define D_HID  512
#define D_OUTF 128
#define M2     8192      // 2*B
#define INV_T  2.0f      // 1/TEMPERATURE
#define BN_EPS 1e-5f
#define L2_EPS 1e-12f

// ---------------- scratch (static device globals; no allocation) ------------
__device__ __align__(128) float g_Y[(size_t)M2 * D_HID];     // 16 MB
__device__ __align__(128) float g_Z[(size_t)M2 * D_OUTF];    // 4 MB
__device__ float g_scale[2][D_HID];
__device__ float g_shift[2][D_HID];
__device__ float g_sumexp[M2];
__device__ float g_pos[B_ROWS];
__device__ float g_loss[1];

// ---------------- init ------------------------------------------------------
__global__ void k_init() {
    int i = blockIdx.x * blockDim.x + threadIdx.x;
    if (i < M2) g_sumexp[i] = 0.f;
    if (i == 0) g_loss[0] = 0.f;
}

// ---------------- GEMM1: Y = concat(h1,h2) @ W1^T + b1 ----------------------
// M=8192, N=512, K=192. BM=BN=128, BK=16, 256 threads, 8x8 microtile.
__global__ __launch_bounds__(256) void k_gemm1(const float* __restrict__ h1,
                                               const float* __restrict__ h2,
                                               const float* __restrict__ W1,
                                               const float* __restrict__ b1) {
    __shared__ __align__(16) float sA[16][128];
    __shared__ __align__(16) float sB[16][128];
    const int t  = threadIdx.x;
    const int tx = t & 15, ty = t >> 4;
    const int m0 = blockIdx.y * 128;
    const int n0 = blockIdx.x * 128;
    const float* A = (m0 < B_ROWS) ? (h1 + (size_t)m0 * D_INF)
                                   : (h2 + (size_t)(m0 - B_ROWS) * D_INF);
    float acc[8][8];
#pragma unroll
    for (int i = 0; i < 8; i++)
#pragma unroll
        for (int j = 0; j < 8; j++) acc[i][j] = 0.f;

    const int lrow = t >> 2;         // 0..63
    const int lkq  = (t & 3) * 4;    // 0,4,8,12

    for (int k0 = 0; k0 < D_INF; k0 += 16) {
#pragma unroll
        for (int p = 0; p < 2; p++) {
            int row = lrow + p * 64;
            float4 va = *(const float4*)(A  + (size_t)row        * D_INF + k0 + lkq);
            float4 vb = *(const float4*)(W1 + (size_t)(n0 + row) * D_INF + k0 + lkq);
            sA[lkq+0][row] = va.x; sA[lkq+1][row] = va.y;
            sA[lkq+2][row] = va.z; sA[lkq+3][row] = va.w;
            sB[lkq+0][row] = vb.x; sB[lkq+1][row] = vb.y;
            sB[lkq+2][row] = vb.z; sB[lkq+3][row] = vb.w;
        }
        __syncthreads();
#pragma unroll
        for (int kk = 0; kk < 16; kk++) {
            float4 a0 = *(const float4*)&sA[kk][ty * 8];
            float4 a1 = *(const float4*)&sA[kk][ty * 8 + 4];
            float4 b0 = *(const float4*)&sB[kk][tx * 8];
            float4 b1v = *(const float4*)&sB[kk][tx * 8 + 4];
            float a[8] = {a0.x,a0.y,a0.z,a0.w,a1.x,a1.y,a1.z,a1.w};
            float b[8] = {b0.x,b0.y,b0.z,b0.w,b1v.x,b1v.y,b1v.z,b1v.w};
#pragma unroll
            for (int i = 0; i < 8; i++)
#pragma unroll
                for (int j = 0; j < 8; j++) acc[i][j] = fmaf(a[i], b[j], acc[i][j]);
        }
        __syncthreads();
    }
#pragma unroll
    for (int i = 0; i < 8; i++) {
        int m = m0 + ty * 8 + i;
#pragma unroll
        for (int j = 0; j < 8; j++) {
            int n = n0 + tx * 8 + j;
            g_Y[(size_t)m * D_HID + n] = acc[i][j] + b1[n];
        }
    }
}

// ---------------- BN stats -> per-column scale/shift (per half) -------------
__global__ void k_bnstats(const float* __restrict__ gamma,
                          const float* __restrict__ beta) {
    const int half = blockIdx.x >> 4;
    const int c  = (blockIdx.x & 15) * 32 + threadIdx.x;
    const int ty = threadIdx.y;
    const float* Yb = g_Y + (size_t)half * B_ROWS * D_HID;
    float s = 0.f, q = 0.f;
    for (int r = ty; r < B_ROWS; r += 8) {
        float v = Yb[(size_t)r * D_HID + c];
        s += v;
        q = fmaf(v, v, q);
    }
    __shared__ float sS[8][32], sQ[8][32];
    sS[ty][threadIdx.x] = s;
    sQ[ty][threadIdx.x] = q;
    __syncthreads();
    if (ty == 0) {
#pragma unroll
        for (int i = 1; i < 8; i++) { s += sS[i][threadIdx.x]; q += sQ[i][threadIdx.x]; }
        float mean = s * (1.f / B_ROWS);
        float var  = q * (1.f / B_ROWS) - mean * mean;
        float sc = gamma[c] * rsqrtf(var + BN_EPS);
        g_scale[half][c] = sc;
        g_shift[half][c] = beta[c] - mean * sc;
    }
}

// ---------------- GEMM2: Z = relu(BN(Y)) @ W2^T + b2, then L2-normalize -----
// M=8192, N=128, K=512. BM=64, BN=128, BK=16, 256 threads, 4x8 microtile.
__global__ __launch_bounds__(256) void k_gemm2(const float* __restrict__ W2,
                                               const float* __restrict__ b2) {
    __shared__ __align__(16) float sA[16][64];
    __shared__ __align__(16) float sB[16][128];
    __shared__ float sRed[64][16];
    const int t  = threadIdx.x;
    const int tx = t & 15, ty = t >> 4;
    const int m0 = blockIdx.x * 64;
    const int half = (m0 >= B_ROWS);
    const float* __restrict__ sc = g_scale[half];
    const float* __restrict__ sh = g_shift[half];

    float acc[4][8];
#pragma unroll
    for (int i = 0; i < 4; i++)
#pragma unroll
        for (int j = 0; j < 8; j++) acc[i][j] = 0.f;

    const int lrow = t >> 2;         // 0..63
    const int lkq  = (t & 3) * 4;

    for (int k0 = 0; k0 < D_HID; k0 += 16) {
        {
            int kb = k0 + lkq;
            float4 va = *(const float4*)(g_Y + (size_t)(m0 + lrow) * D_HID + kb);
            sA[lkq+0][lrow] = fmaxf(fmaf(va.x, sc[kb+0], sh[kb+0]), 0.f);
            sA[lkq+1][lrow] = fmaxf(fmaf(va.y, sc[kb+1], sh[kb+1]), 0.f);
            sA[lkq+2][lrow] = fmaxf(fmaf(va.z, sc[kb+2], sh[kb+2]), 0.f);
            sA[lkq+3][lrow] = fmaxf(fmaf(va.w, sc[kb+3], sh[kb+3]), 0.f);
        }
#pragma unroll
        for (int p = 0; p < 2; p++) {
            int row = lrow + p * 64;
            float4 vb = *(const float4*)(W2 + (size_t)row * D_HID + k0 + lkq);
            sB[lkq+0][row] = vb.x; sB[lkq+1][row] = vb.y;
            sB[lkq+2][row] = vb.z; sB[lkq+3][row] = vb.w;
        }
        __syncthreads();
#pragma unroll
        for (int kk = 0; kk < 16; kk++) {
            float4 a0 = *(const float4*)&sA[kk][ty * 4];
            float4 b0 = *(const float4*)&sB[kk][tx * 8];
            float4 b1v = *(const float4*)&sB[kk][tx * 8 + 4];
            float a[4] = {a0.x,a0.y,a0.z,a0.w};
            float b[8] = {b0.x,b0.y,b0.z,b0.w,b1v.x,b1v.y,b1v.z,b1v.w};
#pragma unroll
            for (int i = 0; i < 4; i++)
#pragma unroll
                for (int j = 0; j < 8; j++) acc[i][j] = fmaf(a[i], b[j], acc[i][j]);
        }
        __syncthreads();
    }

    float z[4][8];
    float rs[4];
#pragma unroll
    for (int i = 0; i < 4; i++) {
        rs[i] = 0.f;
#pragma unroll
        for (int j = 0; j < 8; j++) {
            z[i][j] = acc[i][j] + b2[tx * 8 + j];
            rs[i] = fmaf(z[i][j], z[i][j], rs[i]);
        }
        sRed[ty * 4 + i][tx] = rs[i];
    }
    __syncthreads();
#pragma unroll
    for (int i = 0; i < 4; i++) {
        int row = ty * 4 + i;
        float ss = 0.f;
#pragma unroll
        for (int x = 0; x < 16; x++) ss += sRed[row][x];
        float nrm = sqrtf(ss);
        float inv = 1.f / fmaxf(nrm, L2_EPS);
#pragma unroll
        for (int j = 0; j < 8; j++)
            g_Z[(size_t)(m0 + row) * D_OUTF + tx * 8 + j] = z[i][j] * inv;
    }
}

// ---------------- pos[i] = z1_i . z2_i / T ----------------------------------
__global__ void k_pos() {
    int w    = (blockIdx.x * blockDim.x + threadIdx.x) >> 5;
    int lane = threadIdx.x & 31;
    if (w >= B_ROWS) return;
    float4 a = *(const float4*)(g_Z + (size_t)w * D_OUTF + lane * 4);
    float4 b = *(const float4*)(g_Z + (size_t)(w + B_ROWS) * D_OUTF + lane * 4);
    float d = a.x*b.x + a.y*b.y + a.z*b.z + a.w*b.w;
#pragma unroll
    for (int o = 16; o; o >>= 1) d += __shfl_down_sync(0xffffffffu, d, o);
    if (lane == 0) g_pos[w] = d * INV_T;
}

// ---------------- sim + fused exp + row sum ----------------------------------
// sumexp[i] += sum_j exp(dot(z_i,z_j)/T) over a 128x128 tile; K=128.
__global__ __launch_bounds__(256) void k_sim() {
    __shared__ __align__(16) float sA[16][128];
    __shared__ __align__(16) float sB[16][128];
    const int t  = threadIdx.x;
    const int tx = t & 15, ty = t >> 4;
    const size_t i0 = (size_t)blockIdx.y * 128;
    const size_t j0 = (size_t)blockIdx.x * 128;

    float acc[8][8];
#pragma unroll
    for (int i = 0; i < 8; i++)
#pragma unroll
        for (int j = 0; j < 8; j++) acc[i][j] = 0.f;

    const int lrow = t >> 2;
    const int lkq  = (t & 3) * 4;

    for (int k0 = 0; k0 < D_OUTF; k0 += 16) {
#pragma unroll
        for (int p = 0; p < 2; p++) {
            int row = lrow + p * 64;
            float4 va = *(const float4*)(g_Z + (i0 + row) * D_OUTF + k0 + lkq);
            float4 vb = *(const float4*)(g_Z + (j0 + row) * D_OUTF + k0 + lkq);
            sA[lkq+0][row] = va.x; sA[lkq+1][row] = va.y;
            sA[lkq+2][row] = va.z; sA[lkq+3][row] = va.w;
            sB[lkq+0][row] = vb.x; sB[lkq+1][row] = vb.y;
            sB[lkq+2][row] = vb.z; sB[lkq+3][row] = vb.w;
        }
        __syncthreads();
#pragma unroll
        for (int kk = 0; kk < 16; kk++) {
            float4 a0 = *(const float4*)&sA[kk][ty * 8];
            float4 a1 = *(const float4*)&sA[kk][ty * 8 + 4];
            float4 b0 = *(const float4*)&sB[kk][tx * 8];
            float4 b1v = *(const float4*)&sB[kk][tx * 8 + 4];
            float a[8] = {a0.x,a0.y,a0.z,a0.w,a1.x,a1.y,a1.z,a1.w};
            float b[8] = {b0.x,b0.y,b0.z,b0.w,b1v.x,b1v.y,b1v.z,b1v.w};
#pragma unroll
            for (int i = 0; i < 8; i++)
#pragma unroll
                for (int j = 0; j < 8; j++) acc[i][j] = fmaf(a[i], b[j], acc[i][j]);
        }
        __syncthreads();
    }

    // exp + per-row partial sums
    float rsum[8];
#pragma unroll
    for (int i = 0; i < 8; i++) {
        rsum[i] = 0.f;
#pragma unroll
        for (int j = 0; j < 8; j++) rsum[i] += __expf(acc[i][j] * INV_T);
    }
    // reuse sA (16*128 = 2048 floats) as [128][16] reduction staging
    float* red = &sA[0][0];
#pragma unroll
    for (int i = 0; i < 8; i++) red[(ty * 8 + i) * 16 + tx] = rsum[i];
    __syncthreads();
    if (t < 128) {
        float s = 0.f;
#pragma unroll
        for (int x = 0; x < 16; x++) s += red[t * 16 + x];
        atomicAdd(&g_sumexp[i0 + t], s);
    }
}

// ---------------- finish: loss = mean(lse_i - pos_i) ------------------------
__global__ void k_finish() {
    int w    = (blockIdx.x * blockDim.x + threadIdx.x) >> 5;
    int lane = threadIdx.x & 31;
    if (w >= M2) return;
    float4 a = *(const float4*)(g_Z + (size_t)w * D_OUTF + lane * 4);
    float d = a.x*a.x + a.y*a.y + a.z*a.z + a.w*a.w;
#pragma unroll
    for (int o = 16; o; o >>= 1) d += __shfl_down_sync(0xffffffffu, d, o);
    if (lane == 0) {
        float se  = g_sumexp[w] - __expf(d * INV_T);   // exclude diagonal
        float lse = logf(se);
        float li  = lse - g_pos[w & (B_ROWS - 1)];
        atomicAdd(&g_loss[0], li * (1.f / M2));
    }
}

// ---------------- emit output: [loss, z1, z2] -------------------------------
__global__ void k_copy(float* __restrict__ out, int out_size) {
    int i = blockIdx.x * blockDim.x + threadIdx.x;
    if (i == 0 && out_size > 0) out[0] = g_loss[0];
    const int n = M2 * D_OUTF;
    for (int idx = i; idx < n; idx += gridDim.x * blockDim.x) {
        if (1 + idx < out_size) out[1 + idx] = g_Z[idx];
    }
}

// ---------------- launch -----------------------------------------------------
extern "C" void kernel_launch(void* const* d_in, const int* in_sizes, int n_in,
                              void* d_out, int out_size) {
    const float* h1    = (const float*)d_in[0];
    const float* h2    = (const float*)d_in[1];
    const float* W1    = (const float*)d_in[2];
    const float* b1    = (const float*)d_in[3];
    const float* gamma = (const float*)d_in[4];
    const float* beta  = (const float*)d_in[5];
    const float* W2    = (const float*)d_in[6];
    const float* b2    = (const float*)d_in[7];
    float* out = (float*)d_out;

    k_init<<<32, 256>>>();
    k_gemm1<<<dim3(4, 64), 256>>>(h1, h2, W1, b1);
    k_bnstats<<<32, dim3(32, 8)>>>(gamma, beta);
    k_gemm2<<<128, 256>>>(W2, b2);
    k_pos<<<512, 256>>>();
    k_sim<<<dim3(64, 64), 256>>>();
    k_finish<<<1024, 256>>>();
    k_copy<<<1024, 256>>>(out, out_size);
}

// round 2
// speedup vs baseline: 1.7722x; 1.7722x over previous
#include <cuda_runtime.h>
#include <math.h>

#define B_ROWS 4096
#define D_INF  192
#define D_HID  512
#define D_OUTF 128
#define M2     8192      // 2*B
#define INV_T  2.0f      // 1/TEMPERATURE
#define BN_EPS 1e-5f
#define L2_EPS 1e-12f

// ---------------- scratch (static device globals; no allocation) ------------
__device__ __align__(128) float g_Y[(size_t)M2 * D_HID];     // 16 MB
__device__ __align__(128) float g_Z[(size_t)M2 * D_OUTF];    // 4 MB
__device__ float g_colsum[2][D_HID];
__device__ float g_colsq[2][D_HID];
__device__ float g_scale[2][D_HID];
__device__ float g_shift[2][D_HID];
__device__ float g_sumexp[M2];
__device__ float g_pos[B_ROWS];
__device__ float g_loss[1];

// ---------------- init ------------------------------------------------------
__global__ void k_init() {
    int i = blockIdx.x * blockDim.x + threadIdx.x;
    if (i < M2) g_sumexp[i] = 0.f;
    if (i < 2 * D_HID) {
        g_colsum[i >> 9][i & 511] = 0.f;
        g_colsq [i >> 9][i & 511] = 0.f;
    }
    if (i == 0) g_loss[0] = 0.f;
}

// ---------------- GEMM1: Y = concat(h1,h2) @ W1^T + b1 + fused BN partials --
// M=8192, N=512, K=192. BM=BN=128, BK=16, 256 threads, split 4+4 microtile.
__global__ __launch_bounds__(256, 2) void k_gemm1(const float* __restrict__ h1,
                                                  const float* __restrict__ h2,
                                                  const float* __restrict__ W1,
                                                  const float* __restrict__ b1) {
    __shared__ __align__(16) float sA[16][128];
    __shared__ __align__(16) float sB[16][128];
    __shared__ float redS[128][17];
    __shared__ float redQ[128][17];
    const int t  = threadIdx.x;
    const int tx = t & 15, ty = t >> 4;
    const int m0 = blockIdx.y * 128;
    const int n0 = blockIdx.x * 128;
    const int half = (m0 >= B_ROWS);
    const float* A = half ? (h2 + (size_t)(m0 - B_ROWS) * D_INF)
                          : (h1 + (size_t)m0 * D_INF);
    float acc[8][8];
#pragma unroll
    for (int i = 0; i < 8; i++)
#pragma unroll
        for (int j = 0; j < 8; j++) acc[i][j] = 0.f;

    const int lrow = t >> 2;         // 0..63
    const int lkq  = (t & 3) * 4;    // 0,4,8,12

    for (int k0 = 0; k0 < D_INF; k0 += 16) {
#pragma unroll
        for (int p = 0; p < 2; p++) {
            int row = lrow + p * 64;
            float4 va = *(const float4*)(A  + (size_t)row        * D_INF + k0 + lkq);
            float4 vb = *(const float4*)(W1 + (size_t)(n0 + row) * D_INF + k0 + lkq);
            sA[lkq+0][row] = va.x; sA[lkq+1][row] = va.y;
            sA[lkq+2][row] = va.z; sA[lkq+3][row] = va.w;
            sB[lkq+0][row] = vb.x; sB[lkq+1][row] = vb.y;
            sB[lkq+2][row] = vb.z; sB[lkq+3][row] = vb.w;
        }
        __syncthreads();
#pragma unroll
        for (int kk = 0; kk < 16; kk++) {
            float4 a0 = *(const float4*)&sA[kk][ty * 4];
            float4 a1 = *(const float4*)&sA[kk][ty * 4 + 64];
            float4 b0 = *(const float4*)&sB[kk][tx * 4];
            float4 b1v = *(const float4*)&sB[kk][tx * 4 + 64];
            float a[8] = {a0.x,a0.y,a0.z,a0.w,a1.x,a1.y,a1.z,a1.w};
            float b[8] = {b0.x,b0.y,b0.z,b0.w,b1v.x,b1v.y,b1v.z,b1v.w};
#pragma unroll
            for (int i = 0; i < 8; i++)
#pragma unroll
                for (int j = 0; j < 8; j++) acc[i][j] = fmaf(a[i], b[j], acc[i][j]);
        }
        __syncthreads();
    }

    // epilogue: bias, store Y, accumulate per-column sum/sumsq partials
    float4 bc0 = *(const float4*)&b1[n0 + tx * 4];
    float4 bc1 = *(const float4*)&b1[n0 + tx * 4 + 64];
    float bb[8] = {bc0.x,bc0.y,bc0.z,bc0.w,bc1.x,bc1.y,bc1.z,bc1.w};
    float ps[8], pq[8];
#pragma unroll
    for (int j = 0; j < 8; j++) { ps[j] = 0.f; pq[j] = 0.f; }
#pragma unroll
    for (int i = 0; i < 8; i++) {
        int m = m0 + ty * 4 + (i & 3) + (i >> 2) * 64;
        float y[8];
#pragma unroll
        for (int j = 0; j < 8; j++) {
            y[j] = acc[i][j] + bb[j];
            ps[j] += y[j];
            pq[j] = fmaf(y[j], y[j], pq[j]);
        }
        float4 y0 = {y[0], y[1], y[2], y[3]};
        float4 y1 = {y[4], y[5], y[6], y[7]};
        *(float4*)&g_Y[(size_t)m * D_HID + n0 + tx * 4]      = y0;
        *(float4*)&g_Y[(size_t)m * D_HID + n0 + tx * 4 + 64] = y1;
    }
#pragma unroll
    for (int j = 0; j < 8; j++) {
        int c = tx * 4 + (j & 3) + (j >> 2) * 64;
        redS[c][ty] = ps[j];
        redQ[c][ty] = pq[j];
    }
    __syncthreads();
    if (t < 128) {
        float s = 0.f, q = 0.f;
#pragma unroll
        for (int x = 0; x < 16; x++) { s += redS[t][x]; q += redQ[t][x]; }
        atomicAdd(&g_colsum[half][n0 + t], s);
        atomicAdd(&g_colsq [half][n0 + t], q);
    }
}

// ---------------- finalize BN scale/shift ------------------------------------
__global__ void k_bnfin(const float* __restrict__ gamma,
                        const float* __restrict__ beta) {
    int i = blockIdx.x * blockDim.x + threadIdx.x;
    if (i >= 2 * D_HID) return;
    int half = i >> 9, c = i & 511;
    float mean = g_colsum[half][c] * (1.f / B_ROWS);
    float var  = g_colsq [half][c] * (1.f / B_ROWS) - mean * mean;
    float sc   = gamma[c] * rsqrtf(var + BN_EPS);
    g_scale[half][c] = sc;
    g_shift[half][c] = beta[c] - mean * sc;
}

// ---------------- GEMM2: Z = relu(BN(Y)) @ W2^T + b2, L2-normalize, emit ----
// M=8192, N=128, K=512. BM=32, BN=128, BK=16, 128 threads, 4x8 microtile.
__global__ __launch_bounds__(128) void k_gemm2(const float* __restrict__ W2,
                                               const float* __restrict__ b2,
                                               float* __restrict__ out,
                                               int out_size) {
    __shared__ __align__(16) float sA[16][32];
    __shared__ __align__(16) float sB[16][128];
    __shared__ float ssc[D_HID], ssh[D_HID];
    __shared__ float sRed[32][17];
    __shared__ float sInv[32];
    const int t  = threadIdx.x;
    const int tx = t & 15, ty = t >> 4;     // ty 0..7
    const int m0 = blockIdx.x * 32;
    const int half = (m0 >= B_ROWS);

    {   // preload BN scale/shift (512 floats each, 128 threads x float4)
        int i = t * 4;
        *(float4*)&ssc[i] = *(const float4*)&g_scale[half][i];
        *(float4*)&ssh[i] = *(const float4*)&g_shift[half][i];
    }
    __syncthreads();

    float acc[4][8];
#pragma unroll
    for (int i = 0; i < 4; i++)
#pragma unroll
        for (int j = 0; j < 8; j++) acc[i][j] = 0.f;

    const int lrow = t >> 2;        // 0..31
    const int lkq  = (t & 3) * 4;

    for (int k0 = 0; k0 < D_HID; k0 += 16) {
        int kb = k0 + lkq;
        {
            float4 va = *(const float4*)(g_Y + (size_t)(m0 + lrow) * D_HID + kb);
            sA[lkq+0][lrow] = fmaxf(fmaf(va.x, ssc[kb+0], ssh[kb+0]), 0.f);
            sA[lkq+1][lrow] = fmaxf(fmaf(va.y, ssc[kb+1], ssh[kb+1]), 0.f);
            sA[lkq+2][lrow] = fmaxf(fmaf(va.z, ssc[kb+2], ssh[kb+2]), 0.f);
            sA[lkq+3][lrow] = fmaxf(fmaf(va.w, ssc[kb+3], ssh[kb+3]), 0.f);
        }
#pragma unroll
        for (int p = 0; p < 4; p++) {
            int row = lrow + p * 32;
            float4 vb = *(const float4*)(W2 + (size_t)row * D_HID + kb);
            sB[lkq+0][row] = vb.x; sB[lkq+1][row] = vb.y;
            sB[lkq+2][row] = vb.z; sB[lkq+3][row] = vb.w;
        }
        __syncthreads();
#pragma unroll
        for (int kk = 0; kk < 16; kk++) {
            float4 a0 = *(const float4*)&sA[kk][ty * 4];
            float4 b0 = *(const float4*)&sB[kk][tx * 4];
            float4 b1v = *(const float4*)&sB[kk][tx * 4 + 64];
            float a[4] = {a0.x,a0.y,a0.z,a0.w};
            float b[8] = {b0.x,b0.y,b0.z,b0.w,b1v.x,b1v.y,b1v.z,b1v.w};
#pragma unroll
            for (int i = 0; i < 4; i++)
#pragma unroll
                for (int j = 0; j < 8; j++) acc[i][j] = fmaf(a[i], b[j], acc[i][j]);
        }
        __syncthreads();
    }

    float4 bc0 = *(const float4*)&b2[tx * 4];
    float4 bc1 = *(const float4*)&b2[tx * 4 + 64];
    float bb[8] = {bc0.x,bc0.y,bc0.z,bc0.w,bc1.x,bc1.y,bc1.z,bc1.w};
    float z[4][8];
#pragma unroll
    for (int i = 0; i < 4; i++) {
        float rs = 0.f;
#pragma unroll
        for (int j = 0; j < 8; j++) {
            z[i][j] = acc[i][j] + bb[j];
            rs = fmaf(z[i][j], z[i][j], rs);
        }
        sRed[ty * 4 + i][tx] = rs;
    }
    __syncthreads();
    if (t < 32) {
        float ss = 0.f;
#pragma unroll
        for (int x = 0; x < 16; x++) ss += sRed[t][x];
        sInv[t] = 1.f / fmaxf(sqrtf(ss), L2_EPS);
    }
    __syncthreads();
    bool full = (out_size > M2 * D_OUTF);   // out holds [loss, z1, z2]
#pragma unroll
    for (int i = 0; i < 4; i++) {
        int m = m0 + ty * 4 + i;
        float inv = sInv[ty * 4 + i];
        float zz[8];
#pragma unroll
        for (int j = 0; j < 8; j++) zz[j] = z[i][j] * inv;
        float4 z0 = {zz[0], zz[1], zz[2], zz[3]};
        float4 z1v = {zz[4], zz[5], zz[6], zz[7]};
        *(float4*)&g_Z[(size_t)m * D_OUTF + tx * 4]      = z0;
        *(float4*)&g_Z[(size_t)m * D_OUTF + tx * 4 + 64] = z1v;
        if (full) {
#pragma unroll
            for (int j = 0; j < 8; j++) {
                int c = tx * 4 + (j & 3) + (j >> 2) * 64;
                out[1 + (size_t)m * D_OUTF + c] = zz[j];
            }
        }
    }
}

// ---------------- pos[i] = z1_i . z2_i / T ----------------------------------
__global__ void k_pos() {
    int w    = (blockIdx.x * blockDim.x + threadIdx.x) >> 5;
    int lane = threadIdx.x & 31;
    if (w >= B_ROWS) return;
    float4 a = *(const float4*)(g_Z + (size_t)w * D_OUTF + lane * 4);
    float4 b = *(const float4*)(g_Z + (size_t)(w + B_ROWS) * D_OUTF + lane * 4);
    float d = a.x*b.x + a.y*b.y + a.z*b.z + a.w*b.w;
#pragma unroll
    for (int o = 16; o; o >>= 1) d += __shfl_down_sync(0xffffffffu, d, o);
    if (lane == 0) g_pos[w] = d * INV_T;
}

// ---------------- symmetric sim: exp + row AND col sums ----------------------
__device__ __forceinline__ int tri_off(int r) { return r * 64 - ((r * (r - 1)) >> 1); }

__global__ __launch_bounds__(256, 2) void k_sim() {
    __shared__ __align__(16) float sA[16][128];
    __shared__ __align__(16) float sB[16][128];
    __shared__ float redr[128][17];
    __shared__ float redc[128][17];
    const int t  = threadIdx.x;
    const int tx = t & 15, ty = t >> 4;

    // decode upper-triangular tile index (bi <= bj), 64x64 tile grid
    int tb = blockIdx.x;
    int bi = (int)(64.5f - sqrtf(64.5f * 64.5f - 2.0f * (float)tb));
    if (bi < 0) bi = 0; if (bi > 63) bi = 63;
    while (tri_off(bi + 1) <= tb) ++bi;
    while (tri_off(bi) > tb) --bi;
    int bj = bi + (tb - tri_off(bi));

    const size_t i0 = (size_t)bi * 128;
    const size_t j0 = (size_t)bj * 128;

    float acc[8][8];
#pragma unroll
    for (int i = 0; i < 8; i++)
#pragma unroll
        for (int j = 0; j < 8; j++) acc[i][j] = 0.f;

    const int lrow = t >> 2;
    const int lkq  = (t & 3) * 4;

    for (int k0 = 0; k0 < D_OUTF; k0 += 16) {
#pragma unroll
        for (int p = 0; p < 2; p++) {
            int row = lrow + p * 64;
            float4 va = *(const float4*)(g_Z + (i0 + row) * D_OUTF + k0 + lkq);
            float4 vb = *(const float4*)(g_Z + (j0 + row) * D_OUTF + k0 + lkq);
            sA[lkq+0][row] = va.x; sA[lkq+1][row] = va.y;
            sA[lkq+2][row] = va.z; sA[lkq+3][row] = va.w;
            sB[lkq+0][row] = vb.x; sB[lkq+1][row] = vb.y;
            sB[lkq+2][row] = vb.z; sB[lkq+3][row] = vb.w;
        }
        __syncthreads();
#pragma unroll
        for (int kk = 0; kk < 16; kk++) {
            float4 a0 = *(const float4*)&sA[kk][ty * 4];
            float4 a1 = *(const float4*)&sA[kk][ty * 4 + 64];
            float4 b0 = *(const float4*)&sB[kk][tx * 4];
            float4 b1v = *(const float4*)&sB[kk][tx * 4 + 64];
            float a[8] = {a0.x,a0.y,a0.z,a0.w,a1.x,a1.y,a1.z,a1.w};
            float b[8] = {b0.x,b0.y,b0.z,b0.w,b1v.x,b1v.y,b1v.z,b1v.w};
#pragma unroll
            for (int i = 0; i < 8; i++)
#pragma unroll
                for (int j = 0; j < 8; j++) acc[i][j] = fmaf(a[i], b[j], acc[i][j]);
        }
        __syncthreads();
    }

    // exp + per-row and per-column partial sums (symmetry: col sums feed rows j)
    float rsum[8], csum[8];
#pragma unroll
    for (int i = 0; i < 8; i++) { rsum[i] = 0.f; csum[i] = 0.f; }
#pragma unroll
    for (int i = 0; i < 8; i++)
#pragma unroll
        for (int j = 0; j < 8; j++) {
            float e = __expf(acc[i][j] * INV_T);
            rsum[i] += e;
            csum[j] += e;
        }
#pragma unroll
    for (int i = 0; i < 8; i++) {
        int r = ty * 4 + (i & 3) + (i >> 2) * 64;
        redr[r][tx] = rsum[i];
    }
#pragma unroll
    for (int j = 0; j < 8; j++) {
        int c = tx * 4 + (j & 3) + (j >> 2) * 64;
        redc[c][ty] = csum[j];
    }
    __syncthreads();
    if (t < 128) {
        float s = 0.f;
#pragma unroll
        for (int x = 0; x < 16; x++) s += redr[t][x];
        atomicAdd(&g_sumexp[i0 + t], s);
        if (bi != bj) {
            float c = 0.f;
#pragma unroll
            for (int x = 0; x < 16; x++) c += redc[t][x];
            atomicAdd(&g_sumexp[j0 + t], c);
        }
    }
}

// ---------------- finish: loss = mean(lse_i - pos_i) ------------------------
__global__ void k_finish() {
    int w    = (blockIdx.x * blockDim.x + threadIdx.x) >> 5;
    int lane = threadIdx.x & 31;
    if (w >= M2) return;
    float4 a = *(const float4*)(g_Z + (size_t)w * D_OUTF + lane * 4);
    float d = a.x*a.x + a.y*a.y + a.z*a.z + a.w*a.w;
#pragma unroll
    for (int o = 16; o; o >>= 1) d += __shfl_down_sync(0xffffffffu, d, o);
    if (lane == 0) {
        float se  = g_sumexp[w] - __expf(d * INV_T);   // exclude diagonal
        float lse = logf(se);
        float li  = lse - g_pos[w & (B_ROWS - 1)];
        atomicAdd(&g_loss[0], li * (1.f / M2));
    }
}

// ---------------- emit loss --------------------------------------------------
__global__ void k_out(float* __restrict__ out, int out_size) {
    if (out_size > 0) out[0] = g_loss[0];
}

// ---------------- launch -----------------------------------------------------
extern "C" void kernel_launch(void* const* d_in, const int* in_sizes, int n_in,
                              void* d_out, int out_size) {
    const float* h1    = (const float*)d_in[0];
    const float* h2    = (const float*)d_in[1];
    const float* W1    = (const float*)d_in[2];
    const float* b1    = (const float*)d_in[3];
    const float* gamma = (const float*)d_in[4];
    const float* beta  = (const float*)d_in[5];
    const float* W2    = (const float*)d_in[6];
    const float* b2    = (const float*)d_in[7];
    float* out = (float*)d_out;

    k_init  <<<32, 256>>>();
    k_gemm1 <<<dim3(4, 64), 256>>>(h1, h2, W1, b1);
    k_bnfin <<<4, 256>>>(gamma, beta);
    k_gemm2 <<<256, 128>>>(W2, b2, out, out_size);
    k_pos   <<<512, 256>>>();
    k_sim   <<<2080, 256>>>();
    k_finish<<<1024, 256>>>();
    k_out   <<<1, 1>>>(out, out_size);
}

// round 3
// speedup vs baseline: 1.8367x; 1.0364x over previous
#include <cuda_runtime.h>
#include <math.h>

#define B_ROWS 4096
#define D_INF  192
#define D_HID  512
#define D_OUTF 128
#define M2     8192      // 2*B
#define INV_T  2.0f      // 1/TEMPERATURE
#define BN_EPS 1e-5f
#define L2_EPS 1e-12f

// ---------------- scratch (static device globals; no allocation) ------------
__device__ __align__(128) float g_Y[(size_t)M2 * D_HID];     // 16 MB
__device__ __align__(128) float g_Z[(size_t)M2 * D_OUTF];    // 4 MB
__device__ float g_colsum[2][D_HID];
__device__ float g_colsq[2][D_HID];
__device__ float g_scale[2][D_HID];
__device__ float g_shift[2][D_HID];
__device__ float g_sumexp[M2];
__device__ float g_pos[B_ROWS];
__device__ float g_loss[1];

// ---------------- init ------------------------------------------------------
__global__ void k_init() {
    int i = blockIdx.x * blockDim.x + threadIdx.x;
    if (i < M2) g_sumexp[i] = 0.f;
    if (i < 2 * D_HID) {
        g_colsum[i >> 9][i & 511] = 0.f;
        g_colsq [i >> 9][i & 511] = 0.f;
    }
    if (i == 0) g_loss[0] = 0.f;
}

// ---------------- GEMM1: Y = concat(h1,h2) @ W1^T + b1 + fused BN partials --
// M=8192, N=512, K=192. BM=BN=128, BK=16, 256 threads, double-buffered.
__global__ __launch_bounds__(256, 2) void k_gemm1(const float* __restrict__ h1,
                                                  const float* __restrict__ h2,
                                                  const float* __restrict__ W1,
                                                  const float* __restrict__ b1) {
    __shared__ __align__(16) float sA2[2][16][128];
    __shared__ __align__(16) float sB2[2][16][128];
    const int t  = threadIdx.x;
    const int tx = t & 15, ty = t >> 4;
    const int m0 = blockIdx.y * 128;
    const int n0 = blockIdx.x * 128;
    const int half = (m0 >= B_ROWS);
    const float* A = half ? (h2 + (size_t)(m0 - B_ROWS) * D_INF)
                          : (h1 + (size_t)m0 * D_INF);
    const int lrow = t >> 2;         // 0..63
    const int lkq  = (t & 3) * 4;    // 0,4,8,12

    const float* pA0 = A  + (size_t)lrow        * D_INF + lkq;
    const float* pA1 = A  + (size_t)(lrow + 64) * D_INF + lkq;
    const float* pB0 = W1 + (size_t)(n0 + lrow)      * D_INF + lkq;
    const float* pB1 = W1 + (size_t)(n0 + lrow + 64) * D_INF + lkq;

    float acc[8][8];
#pragma unroll
    for (int i = 0; i < 8; i++)
#pragma unroll
        for (int j = 0; j < 8; j++) acc[i][j] = 0.f;

    float4 va0 = *(const float4*)pA0;
    float4 va1 = *(const float4*)pA1;
    float4 vb0 = *(const float4*)pB0;
    float4 vb1 = *(const float4*)pB1;
    sA2[0][lkq+0][lrow] = va0.x; sA2[0][lkq+1][lrow] = va0.y;
    sA2[0][lkq+2][lrow] = va0.z; sA2[0][lkq+3][lrow] = va0.w;
    sA2[0][lkq+0][lrow+64] = va1.x; sA2[0][lkq+1][lrow+64] = va1.y;
    sA2[0][lkq+2][lrow+64] = va1.z; sA2[0][lkq+3][lrow+64] = va1.w;
    sB2[0][lkq+0][lrow] = vb0.x; sB2[0][lkq+1][lrow] = vb0.y;
    sB2[0][lkq+2][lrow] = vb0.z; sB2[0][lkq+3][lrow] = vb0.w;
    sB2[0][lkq+0][lrow+64] = vb1.x; sB2[0][lkq+1][lrow+64] = vb1.y;
    sB2[0][lkq+2][lrow+64] = vb1.z; sB2[0][lkq+3][lrow+64] = vb1.w;
    __syncthreads();

    const int ITERS = D_INF / 16;   // 12
    for (int it = 0; it < ITERS; it++) {
        int cur = it & 1;
        if (it < ITERS - 1) {
            int off = (it + 1) * 16;
            va0 = *(const float4*)(pA0 + off);
            va1 = *(const float4*)(pA1 + off);
            vb0 = *(const float4*)(pB0 + off);
            vb1 = *(const float4*)(pB1 + off);
        }
#pragma unroll
        for (int kk = 0; kk < 16; kk++) {
            float4 a0 = *(const float4*)&sA2[cur][kk][ty * 4];
            float4 a1 = *(const float4*)&sA2[cur][kk][ty * 4 + 64];
            float4 b0 = *(const float4*)&sB2[cur][kk][tx * 4];
            float4 b1 = *(const float4*)&sB2[cur][kk][tx * 4 + 64];
            float a[8] = {a0.x,a0.y,a0.z,a0.w,a1.x,a1.y,a1.z,a1.w};
            float b[8] = {b0.x,b0.y,b0.z,b0.w,b1.x,b1.y,b1.z,b1.w};
#pragma unroll
            for (int i = 0; i < 8; i++)
#pragma unroll
                for (int j = 0; j < 8; j++) acc[i][j] = fmaf(a[i], b[j], acc[i][j]);
        }
        if (it < ITERS - 1) {
            int nx = cur ^ 1;
            sA2[nx][lkq+0][lrow] = va0.x; sA2[nx][lkq+1][lrow] = va0.y;
            sA2[nx][lkq+2][lrow] = va0.z; sA2[nx][lkq+3][lrow] = va0.w;
            sA2[nx][lkq+0][lrow+64] = va1.x; sA2[nx][lkq+1][lrow+64] = va1.y;
            sA2[nx][lkq+2][lrow+64] = va1.z; sA2[nx][lkq+3][lrow+64] = va1.w;
            sB2[nx][lkq+0][lrow] = vb0.x; sB2[nx][lkq+1][lrow] = vb0.y;
            sB2[nx][lkq+2][lrow] = vb0.z; sB2[nx][lkq+3][lrow] = vb0.w;
            sB2[nx][lkq+0][lrow+64] = vb1.x; sB2[nx][lkq+1][lrow+64] = vb1.y;
            sB2[nx][lkq+2][lrow+64] = vb1.z; sB2[nx][lkq+3][lrow+64] = vb1.w;
            __syncthreads();
        }
    }

    // epilogue: bias, store Y, accumulate per-column sum/sumsq partials
    float4 bc0 = *(const float4*)&b1[n0 + tx * 4];
    float4 bc1 = *(const float4*)&b1[n0 + tx * 4 + 64];
    float bb[8] = {bc0.x,bc0.y,bc0.z,bc0.w,bc1.x,bc1.y,bc1.z,bc1.w};
    float ps[8], pq[8];
#pragma unroll
    for (int j = 0; j < 8; j++) { ps[j] = 0.f; pq[j] = 0.f; }
#pragma unroll
    for (int i = 0; i < 8; i++) {
        int m = m0 + ty * 4 + (i & 3) + (i >> 2) * 64;
        float y[8];
#pragma unroll
        for (int j = 0; j < 8; j++) {
            y[j] = acc[i][j] + bb[j];
            ps[j] += y[j];
            pq[j] = fmaf(y[j], y[j], pq[j]);
        }
        float4 y0 = {y[0], y[1], y[2], y[3]};
        float4 y1 = {y[4], y[5], y[6], y[7]};
        *(float4*)&g_Y[(size_t)m * D_HID + n0 + tx * 4]      = y0;
        *(float4*)&g_Y[(size_t)m * D_HID + n0 + tx * 4 + 64] = y1;
    }
    // alias retired buffers (last compute used buf 1; buf 0 free) as [16][128]
    float (*redS)[128] = reinterpret_cast<float(*)[128]>(&sA2[0][0][0]);
    float (*redQ)[128] = reinterpret_cast<float(*)[128]>(&sB2[0][0][0]);
    __syncthreads();
#pragma unroll
    for (int j = 0; j < 8; j++) {
        int c = tx * 4 + (j & 3) + (j >> 2) * 64;
        redS[ty][c] = ps[j];
        redQ[ty][c] = pq[j];
    }
    __syncthreads();
    if (t < 128) {
        float s = 0.f, q = 0.f;
#pragma unroll
        for (int x = 0; x < 16; x++) { s += redS[x][t]; q += redQ[x][t]; }
        atomicAdd(&g_colsum[half][n0 + t], s);
        atomicAdd(&g_colsq [half][n0 + t], q);
    }
}

// ---------------- finalize BN scale/shift ------------------------------------
__global__ void k_bnfin(const float* __restrict__ gamma,
                        const float* __restrict__ beta) {
    int i = blockIdx.x * blockDim.x + threadIdx.x;
    if (i >= 2 * D_HID) return;
    int half = i >> 9, c = i & 511;
    float mean = g_colsum[half][c] * (1.f / B_ROWS);
    float var  = g_colsq [half][c] * (1.f / B_ROWS) - mean * mean;
    float sc   = gamma[c] * rsqrtf(var + BN_EPS);
    g_scale[half][c] = sc;
    g_shift[half][c] = beta[c] - mean * sc;
}

// ---------------- GEMM2: Z = relu(BN(Y)) @ W2^T + b2, L2-normalize, emit ----
// M=8192, N=128, K=512. BM=32, BN=128, BK=32, 256 threads, double-buffered.
__global__ __launch_bounds__(256) void k_gemm2(const float* __restrict__ W2,
                                               const float* __restrict__ b2,
                                               float* __restrict__ out,
                                               int out_size) {
    __shared__ __align__(16) float sA2[2][32][32];
    __shared__ __align__(16) float sB2[2][32][128];
    __shared__ float ssc[D_HID], ssh[D_HID];
    const int t  = threadIdx.x;
    const int tx = t & 15, ty = t >> 4;     // ty 0..15
    const int m0 = blockIdx.x * 32;
    const int half = (m0 >= B_ROWS);

    const int row8 = t >> 3;        // 0..31
    const int kq8  = (t & 7) * 4;   // 0..28

    if (t < 128) {
        int i = t * 4;
        *(float4*)&ssc[i] = *(const float4*)&g_scale[half][i];
        *(float4*)&ssh[i] = *(const float4*)&g_shift[half][i];
    }
    __syncthreads();

    const float* pA = g_Y + (size_t)(m0 + row8) * D_HID + kq8;
    const float* pB = W2 + (size_t)row8 * D_HID + kq8;

    float4 va, vb[4];
    // initial load (k-base 0)
    {
        float4 r = *(const float4*)pA;
        va.x = fmaxf(fmaf(r.x, ssc[kq8+0], ssh[kq8+0]), 0.f);
        va.y = fmaxf(fmaf(r.y, ssc[kq8+1], ssh[kq8+1]), 0.f);
        va.z = fmaxf(fmaf(r.z, ssc[kq8+2], ssh[kq8+2]), 0.f);
        va.w = fmaxf(fmaf(r.w, ssc[kq8+3], ssh[kq8+3]), 0.f);
#pragma unroll
        for (int p = 0; p < 4; p++)
            vb[p] = *(const float4*)(pB + (size_t)p * 32 * D_HID);
    }
    sA2[0][kq8+0][row8] = va.x; sA2[0][kq8+1][row8] = va.y;
    sA2[0][kq8+2][row8] = va.z; sA2[0][kq8+3][row8] = va.w;
#pragma unroll
    for (int p = 0; p < 4; p++) {
        int nr = row8 + p * 32;
        sB2[0][kq8+0][nr] = vb[p].x; sB2[0][kq8+1][nr] = vb[p].y;
        sB2[0][kq8+2][nr] = vb[p].z; sB2[0][kq8+3][nr] = vb[p].w;
    }
    __syncthreads();

    float acc[2][8];
#pragma unroll
    for (int i = 0; i < 2; i++)
#pragma unroll
        for (int j = 0; j < 8; j++) acc[i][j] = 0.f;

    const int ITERS = D_HID / 32;   // 16
    for (int it = 0; it < ITERS; it++) {
        int cur = it & 1;
        if (it < ITERS - 1) {
            int kb = (it + 1) * 32;
            float4 r = *(const float4*)(pA + kb);
            int kc = kb + kq8;
            va.x = fmaxf(fmaf(r.x, ssc[kc+0], ssh[kc+0]), 0.f);
            va.y = fmaxf(fmaf(r.y, ssc[kc+1], ssh[kc+1]), 0.f);
            va.z = fmaxf(fmaf(r.z, ssc[kc+2], ssh[kc+2]), 0.f);
            va.w = fmaxf(fmaf(r.w, ssc[kc+3], ssh[kc+3]), 0.f);
#pragma unroll
            for (int p = 0; p < 4; p++)
                vb[p] = *(const float4*)(pB + (size_t)p * 32 * D_HID + kb);
        }
#pragma unroll
        for (int kk = 0; kk < 32; kk++) {
            float a0 = sA2[cur][kk][ty * 2];
            float a1 = sA2[cur][kk][ty * 2 + 1];
            float4 b0 = *(const float4*)&sB2[cur][kk][tx * 4];
            float4 b1 = *(const float4*)&sB2[cur][kk][tx * 4 + 64];
            float b[8] = {b0.x,b0.y,b0.z,b0.w,b1.x,b1.y,b1.z,b1.w};
#pragma unroll
            for (int j = 0; j < 8; j++) {
                acc[0][j] = fmaf(a0, b[j], acc[0][j]);
                acc[1][j] = fmaf(a1, b[j], acc[1][j]);
            }
        }
        if (it < ITERS - 1) {
            int nx = cur ^ 1;
            sA2[nx][kq8+0][row8] = va.x; sA2[nx][kq8+1][row8] = va.y;
            sA2[nx][kq8+2][row8] = va.z; sA2[nx][kq8+3][row8] = va.w;
#pragma unroll
            for (int p = 0; p < 4; p++) {
                int nr = row8 + p * 32;
                sB2[nx][kq8+0][nr] = vb[p].x; sB2[nx][kq8+1][nr] = vb[p].y;
                sB2[nx][kq8+2][nr] = vb[p].z; sB2[nx][kq8+3][nr] = vb[p].w;
            }
            __syncthreads();
        }
    }

    float4 bc0 = *(const float4*)&b2[tx * 4];
    float4 bc1 = *(const float4*)&b2[tx * 4 + 64];
    float bb[8] = {bc0.x,bc0.y,bc0.z,bc0.w,bc1.x,bc1.y,bc1.z,bc1.w};
    bool full = (out_size > M2 * D_OUTF);
#pragma unroll
    for (int i = 0; i < 2; i++) {
        float z[8];
        float rs = 0.f;
#pragma unroll
        for (int j = 0; j < 8; j++) {
            z[j] = acc[i][j] + bb[j];
            rs = fmaf(z[j], z[j], rs);
        }
        // reduce across the 16 lanes sharing this row (tx dimension)
#pragma unroll
        for (int o = 8; o; o >>= 1) rs += __shfl_xor_sync(0xffffffffu, rs, o);
        float inv = 1.f / fmaxf(sqrtf(rs), L2_EPS);
        int m = m0 + ty * 2 + i;
#pragma unroll
        for (int j = 0; j < 8; j++) z[j] *= inv;
        float4 z0 = {z[0], z[1], z[2], z[3]};
        float4 z1 = {z[4], z[5], z[6], z[7]};
        *(float4*)&g_Z[(size_t)m * D_OUTF + tx * 4]      = z0;
        *(float4*)&g_Z[(size_t)m * D_OUTF + tx * 4 + 64] = z1;
        if (full) {
#pragma unroll
            for (int j = 0; j < 8; j++) {
                int c = tx * 4 + (j & 3) + (j >> 2) * 64;
                out[1 + (size_t)m * D_OUTF + c] = z[j];
            }
        }
    }
}

// ---------------- pos[i] = z1_i . z2_i / T ----------------------------------
__global__ void k_pos() {
    int w    = (blockIdx.x * blockDim.x + threadIdx.x) >> 5;
    int lane = threadIdx.x & 31;
    if (w >= B_ROWS) return;
    float4 a = *(const float4*)(g_Z + (size_t)w * D_OUTF + lane * 4);
    float4 b = *(const float4*)(g_Z + (size_t)(w + B_ROWS) * D_OUTF + lane * 4);
    float d = a.x*b.x + a.y*b.y + a.z*b.z + a.w*b.w;
#pragma unroll
    for (int o = 16; o; o >>= 1) d += __shfl_down_sync(0xffffffffu, d, o);
    if (lane == 0) g_pos[w] = d * INV_T;
}

// ---------------- symmetric sim: exp + row AND col sums ----------------------
__device__ __forceinline__ int tri_off(int r) { return r * 64 - ((r * (r - 1)) >> 1); }

__global__ __launch_bounds__(256, 2) void k_sim() {
    __shared__ __align__(16) float sA2[2][16][128];
    __shared__ __align__(16) float sB2[2][16][128];
    const int t  = threadIdx.x;
    const int tx = t & 15, ty = t >> 4;

    // decode upper-triangular tile index (bi <= bj), 64x64 tile grid
    int tb = blockIdx.x;
    int bi = (int)(64.5f - sqrtf(64.5f * 64.5f - 2.0f * (float)tb));
    if (bi < 0) bi = 0; if (bi > 63) bi = 63;
    while (tri_off(bi + 1) <= tb) ++bi;
    while (tri_off(bi) > tb) --bi;
    int bj = bi + (tb - tri_off(bi));

    const size_t i0 = (size_t)bi * 128;
    const size_t j0 = (size_t)bj * 128;

    const int lrow = t >> 2;
    const int lkq  = (t & 3) * 4;
    const float* pA0 = g_Z + (i0 + lrow)      * D_OUTF + lkq;
    const float* pA1 = g_Z + (i0 + lrow + 64) * D_OUTF + lkq;
    const float* pB0 = g_Z + (j0 + lrow)      * D_OUTF + lkq;
    const float* pB1 = g_Z + (j0 + lrow + 64) * D_OUTF + lkq;

    float acc[8][8];
#pragma unroll
    for (int i = 0; i < 8; i++)
#pragma unroll
        for (int j = 0; j < 8; j++) acc[i][j] = 0.f;

    float4 va0 = *(const float4*)pA0;
    float4 va1 = *(const float4*)pA1;
    float4 vb0 = *(const float4*)pB0;
    float4 vb1 = *(const float4*)pB1;
    sA2[0][lkq+0][lrow] = va0.x; sA2[0][lkq+1][lrow] = va0.y;
    sA2[0][lkq+2][lrow] = va0.z; sA2[0][lkq+3][lrow] = va0.w;
    sA2[0][lkq+0][lrow+64] = va1.x; sA2[0][lkq+1][lrow+64] = va1.y;
    sA2[0][lkq+2][lrow+64] = va1.z; sA2[0][lkq+3][lrow+64] = va1.w;
    sB2[0][lkq+0][lrow] = vb0.x; sB2[0][lkq+1][lrow] = vb0.y;
    sB2[0][lkq+2][lrow] = vb0.z; sB2[0][lkq+3][lrow] = vb0.w;
    sB2[0][lkq+0][lrow+64] = vb1.x; sB2[0][lkq+1][lrow+64] = vb1.y;
    sB2[0][lkq+2][lrow+64] = vb1.z; sB2[0][lkq+3][lrow+64] = vb1.w;
    __syncthreads();

    const int ITERS = D_OUTF / 16;  // 8
    for (int it = 0; it < ITERS; it++) {
        int cur = it & 1;
        if (it < ITERS - 1) {
            int off = (it + 1) * 16;
            va0 = *(const float4*)(pA0 + off);
            va1 = *(const float4*)(pA1 + off);
            vb0 = *(const float4*)(pB0 + off);
            vb1 = *(const float4*)(pB1 + off);
        }
#pragma unroll
        for (int kk = 0; kk < 16; kk++) {
            float4 a0 = *(const float4*)&sA2[cur][kk][ty * 4];
            float4 a1 = *(const float4*)&sA2[cur][kk][ty * 4 + 64];
            float4 b0 = *(const float4*)&sB2[cur][kk][tx * 4];
            float4 b1 = *(const float4*)&sB2[cur][kk][tx * 4 + 64];
            float a[8] = {a0.x,a0.y,a0.z,a0.w,a1.x,a1.y,a1.z,a1.w};
            float b[8] = {b0.x,b0.y,b0.z,b0.w,b1.x,b1.y,b1.z,b1.w};
#pragma unroll
            for (int i = 0; i < 8; i++)
#pragma unroll
                for (int j = 0; j < 8; j++) acc[i][j] = fmaf(a[i], b[j], acc[i][j]);
        }
        if (it < ITERS - 1) {
            int nx = cur ^ 1;
            sA2[nx][lkq+0][lrow] = va0.x; sA2[nx][lkq+1][lrow] = va0.y;
            sA2[nx][lkq+2][lrow] = va0.z; sA2[nx][lkq+3][lrow] = va0.w;
            sA2[nx][lkq+0][lrow+64] = va1.x; sA2[nx][lkq+1][lrow+64] = va1.y;
            sA2[nx][lkq+2][lrow+64] = va1.z; sA2[nx][lkq+3][lrow+64] = va1.w;
            sB2[nx][lkq+0][lrow] = vb0.x; sB2[nx][lkq+1][lrow] = vb0.y;
            sB2[nx][lkq+2][lrow] = vb0.z; sB2[nx][lkq+3][lrow] = vb0.w;
            sB2[nx][lkq+0][lrow+64] = vb1.x; sB2[nx][lkq+1][lrow+64] = vb1.y;
            sB2[nx][lkq+2][lrow+64] = vb1.z; sB2[nx][lkq+3][lrow+64] = vb1.w;
            __syncthreads();
        }
    }

    // exp + per-row (shuffle) and per-column (smem) sums
    float rsum[8], csum[8];
#pragma unroll
    for (int i = 0; i < 8; i++) { rsum[i] = 0.f; csum[i] = 0.f; }
#pragma unroll
    for (int i = 0; i < 8; i++)
#pragma unroll
        for (int j = 0; j < 8; j++) {
            float e = __expf(acc[i][j] * INV_T);
            rsum[i] += e;
            csum[j] += e;
        }
    // rows: reduce across tx (16 lanes of the half-warp)
#pragma unroll
    for (int i = 0; i < 8; i++) {
#pragma unroll
        for (int o = 8; o; o >>= 1) rsum[i] += __shfl_xor_sync(0xffffffffu, rsum[i], o);
    }
    if (tx == 0) {
#pragma unroll
        for (int i = 0; i < 8; i++) {
            int r = ty * 4 + (i & 3) + (i >> 2) * 64;
            atomicAdd(&g_sumexp[i0 + r], rsum[i]);
        }
    }
    // cols: cross-warp; alias retired buffer sA2[0] (last compute used buf 1)
    if (bi != bj) {
        float (*redc)[128] = reinterpret_cast<float(*)[128]>(&sA2[0][0][0]);
#pragma unroll
        for (int j = 0; j < 8; j++) {
            int c = tx * 4 + (j & 3) + (j >> 2) * 64;
            redc[ty][c] = csum[j];
        }
        __syncthreads();
        if (t < 128) {
            float cs = 0.f;
#pragma unroll
            for (int x = 0; x < 16; x++) cs += redc[x][t];
            atomicAdd(&g_sumexp[j0 + t], cs);
        }
    }
}

// ---------------- finish: loss = mean(lse_i - pos_i) ------------------------
__global__ void k_finish() {
    int w    = (blockIdx.x * blockDim.x + threadIdx.x) >> 5;
    int lane = threadIdx.x & 31;
    if (w >= M2) return;
    float4 a = *(const float4*)(g_Z + (size_t)w * D_OUTF + lane * 4);
    float d = a.x*a.x + a.y*a.y + a.z*a.z + a.w*a.w;
#pragma unroll
    for (int o = 16; o; o >>= 1) d += __shfl_down_sync(0xffffffffu, d, o);
    if (lane == 0) {
        float se  = g_sumexp[w] - __expf(d * INV_T);   // exclude diagonal
        float lse = logf(se);
        float li  = lse - g_pos[w & (B_ROWS - 1)];
        atomicAdd(&g_loss[0], li * (1.f / M2));
    }
}

// ---------------- emit loss --------------------------------------------------
__global__ void k_out(float* __restrict__ out, int out_size) {
    if (out_size > 0) out[0] = g_loss[0];
}

// ---------------- launch -----------------------------------------------------
extern "C" void kernel_launch(void* const* d_in, const int* in_sizes, int n_in,
                              void* d_out, int out_size) {
    const float* h1    = (const float*)d_in[0];
    const float* h2    = (const float*)d_in[1];
    const float* W1    = (const float*)d_in[2];
    const float* b1    = (const float*)d_in[3];
    const float* gamma = (const float*)d_in[4];
    const float* beta  = (const float*)d_in[5];
    const float* W2    = (const float*)d_in[6];
    const float* b2    = (const float*)d_in[7];
    float* out = (float*)d_out;

    k_init  <<<32, 256>>>();
    k_gemm1 <<<dim3(4, 64), 256>>>(h1, h2, W1, b1);
    k_bnfin <<<4, 256>>>(gamma, beta);
    k_gemm2 <<<256, 256>>>(W2, b2, out, out_size);
    k_pos   <<<512, 256>>>();
    k_sim   <<<2080, 256>>>();
    k_finish<<<1024, 256>>>();
    k_out   <<<1, 1>>>(out, out_size);
}

// round 5
// speedup vs baseline: 3.2617x; 1.7758x over previous
#include <cuda_runtime.h>
#include <cuda_bf16.h>
#include <math.h>
#include <stdint.h>

#define B_ROWS 4096
#define D_INF  192
#define D_HID  512
#define D_OUTF 128
#define M2     8192      // 2*B
#define INV_T  2.0f      // 1/TEMPERATURE
#define BN_EPS 1e-5f
#define L2_EPS 1e-12f

// ---------------- scratch (static device globals; no allocation) ------------
__device__ __align__(128) float g_Y[(size_t)M2 * D_HID];     // 16 MB
__device__ __align__(128) float g_Z[(size_t)M2 * D_OUTF];    // 4 MB
__device__ __align__(128) __nv_bfloat16 g_Zh[(size_t)M2 * D_OUTF]; // 2 MB
__device__ float g_colsum[2][D_HID];
__device__ float g_colsq[2][D_HID];
__device__ float g_scale[2][D_HID];
__device__ float g_shift[2][D_HID];
__device__ float g_sumexp[M2];
__device__ float g_pos[B_ROWS];
__device__ float g_loss[1];

// ---------------- init ------------------------------------------------------
__global__ void k_init() {
    int i = blockIdx.x * blockDim.x + threadIdx.x;
    if (i < M2) g_sumexp[i] = 0.f;
    if (i < 2 * D_HID) {
        g_colsum[i >> 9][i & 511] = 0.f;
        g_colsq [i >> 9][i & 511] = 0.f;
    }
    if (i == 0) g_loss[0] = 0.f;
}

// ---------------- GEMM1: Y = concat(h1,h2) @ W1^T + b1 + fused BN partials --
__global__ __launch_bounds__(256, 2) void k_gemm1(const float* __restrict__ h1,
                                                  const float* __restrict__ h2,
                                                  const float* __restrict__ W1,
                                                  const float* __restrict__ b1) {
    __shared__ __align__(16) float sA2[2][16][128];
    __shared__ __align__(16) float sB2[2][16][128];
    const int t  = threadIdx.x;
    const int tx = t & 15, ty = t >> 4;
    const int m0 = blockIdx.y * 128;
    const int n0 = blockIdx.x * 128;
    const int half = (m0 >= B_ROWS);
    const float* A = half ? (h2 + (size_t)(m0 - B_ROWS) * D_INF)
                          : (h1 + (size_t)m0 * D_INF);
    const int lrow = t >> 2;
    const int lkq  = (t & 3) * 4;

    const float* pA0 = A  + (size_t)lrow        * D_INF + lkq;
    const float* pA1 = A  + (size_t)(lrow + 64) * D_INF + lkq;
    const float* pB0 = W1 + (size_t)(n0 + lrow)      * D_INF + lkq;
    const float* pB1 = W1 + (size_t)(n0 + lrow + 64) * D_INF + lkq;

    float acc[8][8];
#pragma unroll
    for (int i = 0; i < 8; i++)
#pragma unroll
        for (int j = 0; j < 8; j++) acc[i][j] = 0.f;

    float4 va0 = *(const float4*)pA0;
    float4 va1 = *(const float4*)pA1;
    float4 vb0 = *(const float4*)pB0;
    float4 vb1 = *(const float4*)pB1;
    sA2[0][lkq+0][lrow] = va0.x; sA2[0][lkq+1][lrow] = va0.y;
    sA2[0][lkq+2][lrow] = va0.z; sA2[0][lkq+3][lrow] = va0.w;
    sA2[0][lkq+0][lrow+64] = va1.x; sA2[0][lkq+1][lrow+64] = va1.y;
    sA2[0][lkq+2][lrow+64] = va1.z; sA2[0][lkq+3][lrow+64] = va1.w;
    sB2[0][lkq+0][lrow] = vb0.x; sB2[0][lkq+1][lrow] = vb0.y;
    sB2[0][lkq+2][lrow] = vb0.z; sB2[0][lkq+3][lrow] = vb0.w;
    sB2[0][lkq+0][lrow+64] = vb1.x; sB2[0][lkq+1][lrow+64] = vb1.y;
    sB2[0][lkq+2][lrow+64] = vb1.z; sB2[0][lkq+3][lrow+64] = vb1.w;
    __syncthreads();

    const int ITERS = D_INF / 16;   // 12
    for (int it = 0; it < ITERS; it++) {
        int cur = it & 1;
        if (it < ITERS - 1) {
            int off = (it + 1) * 16;
            va0 = *(const float4*)(pA0 + off);
            va1 = *(const float4*)(pA1 + off);
            vb0 = *(const float4*)(pB0 + off);
            vb1 = *(const float4*)(pB1 + off);
        }
#pragma unroll
        for (int kk = 0; kk < 16; kk++) {
            float4 a0 = *(const float4*)&sA2[cur][kk][ty * 4];
            float4 a1 = *(const float4*)&sA2[cur][kk][ty * 4 + 64];
            float4 b0 = *(const float4*)&sB2[cur][kk][tx * 4];
            float4 b1 = *(const float4*)&sB2[cur][kk][tx * 4 + 64];
            float a[8] = {a0.x,a0.y,a0.z,a0.w,a1.x,a1.y,a1.z,a1.w};
            float b[8] = {b0.x,b0.y,b0.z,b0.w,b1.x,b1.y,b1.z,b1.w};
#pragma unroll
            for (int i = 0; i < 8; i++)
#pragma unroll
                for (int j = 0; j < 8; j++) acc[i][j] = fmaf(a[i], b[j], acc[i][j]);
        }
        if (it < ITERS - 1) {
            int nx = cur ^ 1;
            sA2[nx][lkq+0][lrow] = va0.x; sA2[nx][lkq+1][lrow] = va0.y;
            sA2[nx][lkq+2][lrow] = va0.z; sA2[nx][lkq+3][lrow] = va0.w;
            sA2[nx][lkq+0][lrow+64] = va1.x; sA2[nx][lkq+1][lrow+64] = va1.y;
            sA2[nx][lkq+2][lrow+64] = va1.z; sA2[nx][lkq+3][lrow+64] = va1.w;
            sB2[nx][lkq+0][lrow] = vb0.x; sB2[nx][lkq+1][lrow] = vb0.y;
            sB2[nx][lkq+2][lrow] = vb0.z; sB2[nx][lkq+3][lrow] = vb0.w;
            sB2[nx][lkq+0][lrow+64] = vb1.x; sB2[nx][lkq+1][lrow+64] = vb1.y;
            sB2[nx][lkq+2][lrow+64] = vb1.z; sB2[nx][lkq+3][lrow+64] = vb1.w;
            __syncthreads();
        }
    }

    float4 bc0 = *(const float4*)&b1[n0 + tx * 4];
    float4 bc1 = *(const float4*)&b1[n0 + tx * 4 + 64];
    float bb[8] = {bc0.x,bc0.y,bc0.z,bc0.w,bc1.x,bc1.y,bc1.z,bc1.w};
    float ps[8], pq[8];
#pragma unroll
    for (int j = 0; j < 8; j++) { ps[j] = 0.f; pq[j] = 0.f; }
#pragma unroll
    for (int i = 0; i < 8; i++) {
        int m = m0 + ty * 4 + (i & 3) + (i >> 2) * 64;
        float y[8];
#pragma unroll
        for (int j = 0; j < 8; j++) {
            y[j] = acc[i][j] + bb[j];
            ps[j] += y[j];
            pq[j] = fmaf(y[j], y[j], pq[j]);
        }
        float4 y0 = {y[0], y[1], y[2], y[3]};
        float4 y1 = {y[4], y[5], y[6], y[7]};
        *(float4*)&g_Y[(size_t)m * D_HID + n0 + tx * 4]      = y0;
        *(float4*)&g_Y[(size_t)m * D_HID + n0 + tx * 4 + 64] = y1;
    }
    float (*redS)[128] = reinterpret_cast<float(*)[128]>(&sA2[0][0][0]);
    float (*redQ)[128] = reinterpret_cast<float(*)[128]>(&sB2[0][0][0]);
    __syncthreads();
#pragma unroll
    for (int j = 0; j < 8; j++) {
        int c = tx * 4 + (j & 3) + (j >> 2) * 64;
        redS[ty][c] = ps[j];
        redQ[ty][c] = pq[j];
    }
    __syncthreads();
    if (t < 128) {
        float s = 0.f, q = 0.f;
#pragma unroll
        for (int x = 0; x < 16; x++) { s += redS[x][t]; q += redQ[x][t]; }
        atomicAdd(&g_colsum[half][n0 + t], s);
        atomicAdd(&g_colsq [half][n0 + t], q);
    }
}

// ---------------- finalize BN scale/shift ------------------------------------
__global__ void k_bnfin(const float* __restrict__ gamma,
                        const float* __restrict__ beta) {
    int i = blockIdx.x * blockDim.x + threadIdx.x;
    if (i >= 2 * D_HID) return;
    int half = i >> 9, c = i & 511;
    float mean = g_colsum[half][c] * (1.f / B_ROWS);
    float var  = g_colsq [half][c] * (1.f / B_ROWS) - mean * mean;
    float sc   = gamma[c] * rsqrtf(var + BN_EPS);
    g_scale[half][c] = sc;
    g_shift[half][c] = beta[c] - mean * sc;
}

// ---------------- GEMM2: Z = relu(BN(Y)) @ W2^T + b2, L2-norm, emit ----------
__global__ __launch_bounds__(256) void k_gemm2(const float* __restrict__ W2,
                                               const float* __restrict__ b2,
                                               float* __restrict__ out,
                                               int out_size) {
    __shared__ __align__(16) float sA2[2][32][32];
    __shared__ __align__(16) float sB2[2][32][128];
    __shared__ float ssc[D_HID], ssh[D_HID];
    const int t  = threadIdx.x;
    const int tx = t & 15, ty = t >> 4;
    const int m0 = blockIdx.x * 32;
    const int half = (m0 >= B_ROWS);

    const int row8 = t >> 3;
    const int kq8  = (t & 7) * 4;

    if (t < 128) {
        int i = t * 4;
        *(float4*)&ssc[i] = *(const float4*)&g_scale[half][i];
        *(float4*)&ssh[i] = *(const float4*)&g_shift[half][i];
    }
    __syncthreads();

    const float* pA = g_Y + (size_t)(m0 + row8) * D_HID + kq8;
    const float* pB = W2 + (size_t)row8 * D_HID + kq8;

    float4 va, vb[4];
    {
        float4 r = *(const float4*)pA;
        va.x = fmaxf(fmaf(r.x, ssc[kq8+0], ssh[kq8+0]), 0.f);
        va.y = fmaxf(fmaf(r.y, ssc[kq8+1], ssh[kq8+1]), 0.f);
        va.z = fmaxf(fmaf(r.z, ssc[kq8+2], ssh[kq8+2]), 0.f);
        va.w = fmaxf(fmaf(r.w, ssc[kq8+3], ssh[kq8+3]), 0.f);
#pragma unroll
        for (int p = 0; p < 4; p++)
            vb[p] = *(const float4*)(pB + (size_t)p * 32 * D_HID);
    }
    sA2[0][kq8+0][row8] = va.x; sA2[0][kq8+1][row8] = va.y;
    sA2[0][kq8+2][row8] = va.z; sA2[0][kq8+3][row8] = va.w;
#pragma unroll
    for (int p = 0; p < 4; p++) {
        int nr = row8 + p * 32;
        sB2[0][kq8+0][nr] = vb[p].x; sB2[0][kq8+1][nr] = vb[p].y;
        sB2[0][kq8+2][nr] = vb[p].z; sB2[0][kq8+3][nr] = vb[p].w;
    }
    __syncthreads();

    float acc[2][8];
#pragma unroll
    for (int i = 0; i < 2; i++)
#pragma unroll
        for (int j = 0; j < 8; j++) acc[i][j] = 0.f;

    const int ITERS = D_HID / 32;   // 16
    for (int it = 0; it < ITERS; it++) {
        int cur = it & 1;
        if (it < ITERS - 1) {
            int kb = (it + 1) * 32;
            float4 r = *(const float4*)(pA + kb);
            int kc = kb + kq8;
            va.x = fmaxf(fmaf(r.x, ssc[kc+0], ssh[kc+0]), 0.f);
            va.y = fmaxf(fmaf(r.y, ssc[kc+1], ssh[kc+1]), 0.f);
            va.z = fmaxf(fmaf(r.z, ssc[kc+2], ssh[kc+2]), 0.f);
            va.w = fmaxf(fmaf(r.w, ssc[kc+3], ssh[kc+3]), 0.f);
#pragma unroll
            for (int p = 0; p < 4; p++)
                vb[p] = *(const float4*)(pB + (size_t)p * 32 * D_HID + kb);
        }
#pragma unroll
        for (int kk = 0; kk < 32; kk++) {
            float a0 = sA2[cur][kk][ty * 2];
            float a1 = sA2[cur][kk][ty * 2 + 1];
            float4 b0 = *(const float4*)&sB2[cur][kk][tx * 4];
            float4 b1 = *(const float4*)&sB2[cur][kk][tx * 4 + 64];
            float b[8] = {b0.x,b0.y,b0.z,b0.w,b1.x,b1.y,b1.z,b1.w};
#pragma unroll
            for (int j = 0; j < 8; j++) {
                acc[0][j] = fmaf(a0, b[j], acc[0][j]);
                acc[1][j] = fmaf(a1, b[j], acc[1][j]);
            }
        }
        if (it < ITERS - 1) {
            int nx = cur ^ 1;
            sA2[nx][kq8+0][row8] = va.x; sA2[nx][kq8+1][row8] = va.y;
            sA2[nx][kq8+2][row8] = va.z; sA2[nx][kq8+3][row8] = va.w;
#pragma unroll
            for (int p = 0; p < 4; p++) {
                int nr = row8 + p * 32;
                sB2[nx][kq8+0][nr] = vb[p].x; sB2[nx][kq8+1][nr] = vb[p].y;
                sB2[nx][kq8+2][nr] = vb[p].z; sB2[nx][kq8+3][nr] = vb[p].w;
            }
            __syncthreads();
        }
    }

    float4 bc0 = *(const float4*)&b2[tx * 4];
    float4 bc1 = *(const float4*)&b2[tx * 4 + 64];
    float bb[8] = {bc0.x,bc0.y,bc0.z,bc0.w,bc1.x,bc1.y,bc1.z,bc1.w};
    bool full = (out_size > M2 * D_OUTF);
#pragma unroll
    for (int i = 0; i < 2; i++) {
        float z[8];
        float rs = 0.f;
#pragma unroll
        for (int j = 0; j < 8; j++) {
            z[j] = acc[i][j] + bb[j];
            rs = fmaf(z[j], z[j], rs);
        }
#pragma unroll
        for (int o = 8; o; o >>= 1) rs += __shfl_xor_sync(0xffffffffu, rs, o);
        float inv = 1.f / fmaxf(sqrtf(rs), L2_EPS);
        int m = m0 + ty * 2 + i;
#pragma unroll
        for (int j = 0; j < 8; j++) z[j] *= inv;
        float4 z0 = {z[0], z[1], z[2], z[3]};
        float4 z1 = {z[4], z[5], z[6], z[7]};
        *(float4*)&g_Z[(size_t)m * D_OUTF + tx * 4]      = z0;
        *(float4*)&g_Z[(size_t)m * D_OUTF + tx * 4 + 64] = z1;
        __nv_bfloat162* zh0 = (__nv_bfloat162*)&g_Zh[(size_t)m * D_OUTF + tx * 4];
        __nv_bfloat162* zh1 = (__nv_bfloat162*)&g_Zh[(size_t)m * D_OUTF + tx * 4 + 64];
        zh0[0] = __floats2bfloat162_rn(z[0], z[1]);
        zh0[1] = __floats2bfloat162_rn(z[2], z[3]);
        zh1[0] = __floats2bfloat162_rn(z[4], z[5]);
        zh1[1] = __floats2bfloat162_rn(z[6], z[7]);
        if (full) {
#pragma unroll
            for (int j = 0; j < 8; j++) {
                int c = tx * 4 + (j & 3) + (j >> 2) * 64;
                out[1 + (size_t)m * D_OUTF + c] = z[j];
            }
        }
    }
}

// ---------------- pos[i] = z1_i . z2_i / T ----------------------------------
__global__ void k_pos() {
    int w    = (blockIdx.x * blockDim.x + threadIdx.x) >> 5;
    int lane = threadIdx.x & 31;
    if (w >= B_ROWS) return;
    float4 a = *(const float4*)(g_Z + (size_t)w * D_OUTF + lane * 4);
    float4 b = *(const float4*)(g_Z + (size_t)(w + B_ROWS) * D_OUTF + lane * 4);
    float d = a.x*b.x + a.y*b.y + a.z*b.z + a.w*b.w;
#pragma unroll
    for (int o = 16; o; o >>= 1) d += __shfl_down_sync(0xffffffffu, d, o);
    if (lane == 0) g_pos[w] = d * INV_T;
}

// ---------------- tensor-core sim via mma.sync (bf16, fp32 accum) -----------
// Triangular 128x128 tiles. 8 warps (2m x 4n), warp tile 64x32, m16n8k16.
// SMEM: bf16 tiles with 136-element row pitch (conflict-free fragment LDS).
#define SIM_PITCH 136
#define SIM_TILE_BYTES (128 * SIM_PITCH * 2)   // 34816
#define SIM_SMEM_SIZE (2 * SIM_TILE_BYTES + 2 * 128 * 4)

__device__ __forceinline__ int tri_off(int r) { return r * 64 - ((r * (r - 1)) >> 1); }

__global__ __launch_bounds__(256) void k_simw() {
    extern __shared__ __align__(16) char smem[];
    __nv_bfloat16* sA = (__nv_bfloat16*)smem;
    __nv_bfloat16* sB = (__nv_bfloat16*)(smem + SIM_TILE_BYTES);
    float* srow = (float*)(smem + 2 * SIM_TILE_BYTES);
    float* scol = srow + 128;
    const uint32_t* sAw = (const uint32_t*)sA;
    const uint32_t* sBw = (const uint32_t*)sB;

    const int t = threadIdx.x;
    const int wid = t >> 5, lane = t & 31;
    const int gr = lane >> 2;        // group row 0..7
    const int qq = lane & 3;         // quad col 0..3
    const int warp_m = wid >> 2;     // 0..1
    const int warp_n = wid & 3;      // 0..3

    // decode upper-triangular tile (bi <= bj), 64x64 grid
    int tb = blockIdx.x;
    int bi = (int)(64.5f - sqrtf(64.5f * 64.5f - 2.0f * (float)tb));
    if (bi < 0) bi = 0; if (bi > 63) bi = 63;
    while (tri_off(bi + 1) <= tb) ++bi;
    while (tri_off(bi) > tb) --bi;
    int bj = bi + (tb - tri_off(bi));
    const size_t i0 = (size_t)bi * 128;
    const size_t j0 = (size_t)bj * 128;

    if (t < 128) { srow[t] = 0.f; scol[t] = 0.f; }

    // stage tiles: 128 rows x 256B each = 2048 uint4 per tile
#pragma unroll
    for (int it = 0; it < 8; it++) {
        int q   = t + it * 256;
        int row = q >> 4;
        int cb  = q & 15;
        uint4 va = *(const uint4*)(g_Zh + (i0 + row) * D_OUTF + cb * 8);
        uint4 vb = *(const uint4*)(g_Zh + (j0 + row) * D_OUTF + cb * 8);
        *(uint4*)((char*)sA + row * (SIM_PITCH * 2) + cb * 16) = va;
        *(uint4*)((char*)sB + row * (SIM_PITCH * 2) + cb * 16) = vb;
    }
    __syncthreads();

    float c[4][4][4];
#pragma unroll
    for (int mi = 0; mi < 4; mi++)
#pragma unroll
        for (int ni = 0; ni < 4; ni++)
#pragma unroll
            for (int r = 0; r < 4; r++) c[mi][ni][r] = 0.f;

    const int PW = SIM_PITCH / 2;    // 68 words per row
#pragma unroll
    for (int ks = 0; ks < 8; ks++) {
        int kw = ks * 8 + qq;        // word offset within row
        uint32_t a[4][4], b[4][2];
#pragma unroll
        for (int mi = 0; mi < 4; mi++) {
            int r0 = warp_m * 64 + mi * 16 + gr;
            a[mi][0] = sAw[r0 * PW + kw];
            a[mi][1] = sAw[(r0 + 8) * PW + kw];
            a[mi][2] = sAw[r0 * PW + kw + 4];
            a[mi][3] = sAw[(r0 + 8) * PW + kw + 4];
        }
#pragma unroll
        for (int ni = 0; ni < 4; ni++) {
            int n0 = warp_n * 32 + ni * 8 + gr;
            b[ni][0] = sBw[n0 * PW + kw];
            b[ni][1] = sBw[n0 * PW + kw + 4];
        }
#pragma unroll
        for (int mi = 0; mi < 4; mi++)
#pragma unroll
            for (int ni = 0; ni < 4; ni++) {
                asm volatile(
                    "mma.sync.aligned.m16n8k16.row.col.f32.bf16.bf16.f32 "
                    "{%0,%1,%2,%3}, {%4,%5,%6,%7}, {%8,%9}, {%0,%1,%2,%3};"
                    : "+f"(c[mi][ni][0]), "+f"(c[mi][ni][1]),
                      "+f"(c[mi][ni][2]), "+f"(c[mi][ni][3])
                    : "r"(a[mi][0]), "r"(a[mi][1]), "r"(a[mi][2]), "r"(a[mi][3]),
                      "r"(b[ni][0]), "r"(b[ni][1]));
            }
    }

    // exp + row/col partial sums
    // thread's D elements: row = warp_m*64+mi*16+gr (+8 for regs 2,3),
    //                      col = warp_n*32+ni*8+qq*2 (+1 for regs 1,3)
    float rsum[8], csum[8];
#pragma unroll
    for (int i = 0; i < 8; i++) { rsum[i] = 0.f; csum[i] = 0.f; }
#pragma unroll
    for (int mi = 0; mi < 4; mi++)
#pragma unroll
        for (int ni = 0; ni < 4; ni++) {
            float e0 = __expf(c[mi][ni][0] * INV_T);
            float e1 = __expf(c[mi][ni][1] * INV_T);
            float e2 = __expf(c[mi][ni][2] * INV_T);
            float e3 = __expf(c[mi][ni][3] * INV_T);
            rsum[mi * 2 + 0] += e0 + e1;
            rsum[mi * 2 + 1] += e2 + e3;
            csum[ni * 2 + 0] += e0 + e2;
            csum[ni * 2 + 1] += e1 + e3;
        }
    // rows: reduce over the 4 lanes of each quad (qq)
#pragma unroll
    for (int i = 0; i < 8; i++) {
        rsum[i] += __shfl_xor_sync(0xffffffffu, rsum[i], 1);
        rsum[i] += __shfl_xor_sync(0xffffffffu, rsum[i], 2);
    }
    if (qq == 0) {
#pragma unroll
        for (int mi = 0; mi < 4; mi++) {
            atomicAdd(&srow[warp_m * 64 + mi * 16 + gr],     rsum[mi * 2 + 0]);
            atomicAdd(&srow[warp_m * 64 + mi * 16 + gr + 8], rsum[mi * 2 + 1]);
        }
    }
    // cols: reduce over gr (lanes stride 4)
#pragma unroll
    for (int i = 0; i < 8; i++) {
        csum[i] += __shfl_xor_sync(0xffffffffu, csum[i], 4);
        csum[i] += __shfl_xor_sync(0xffffffffu, csum[i], 8);
        csum[i] += __shfl_xor_sync(0xffffffffu, csum[i], 16);
    }
    if (gr == 0) {
#pragma unroll
        for (int ni = 0; ni < 4; ni++) {
            atomicAdd(&scol[warp_n * 32 + ni * 8 + qq * 2],     csum[ni * 2 + 0]);
            atomicAdd(&scol[warp_n * 32 + ni * 8 + qq * 2 + 1], csum[ni * 2 + 1]);
        }
    }
    __syncthreads();
    if (t < 128) {
        atomicAdd(&g_sumexp[i0 + t], srow[t]);
        if (bi != bj) atomicAdd(&g_sumexp[j0 + t], scol[t]);
    }
}

// ---------------- finish: loss = mean(lse_i - pos_i) ------------------------
// diagonal term from bf16 z to match the MMA-summed diagonal
__global__ void k_finish() {
    int w    = (blockIdx.x * blockDim.x + threadIdx.x) >> 5;
    int lane = threadIdx.x & 31;
    if (w >= M2) return;
    const __nv_bfloat16* zr = g_Zh + (size_t)w * D_OUTF + lane * 4;
    float d = 0.f;
#pragma unroll
    for (int j = 0; j < 4; j++) {
        float v = __bfloat162float(zr[j]);
        d = fmaf(v, v, d);
    }
#pragma unroll
    for (int o = 16; o; o >>= 1) d += __shfl_down_sync(0xffffffffu, d, o);
    if (lane == 0) {
        float se  = g_sumexp[w] - __expf(d * INV_T);   // exclude diagonal
        float lse = logf(se);
        float li  = lse - g_pos[w & (B_ROWS - 1)];
        atomicAdd(&g_loss[0], li * (1.f / M2));
    }
}

// ---------------- emit loss --------------------------------------------------
__global__ void k_out(float* __restrict__ out, int out_size) {
    if (out_size > 0) out[0] = g_loss[0];
}

// ---------------- launch -----------------------------------------------------
extern "C" void kernel_launch(void* const* d_in, const int* in_sizes, int n_in,
                              void* d_out, int out_size) {
    const float* h1    = (const float*)d_in[0];
    const float* h2    = (const float*)d_in[1];
    const float* W1    = (const float*)d_in[2];
    const float* b1    = (const float*)d_in[3];
    const float* gamma = (const float*)d_in[4];
    const float* beta  = (const float*)d_in[5];
    const float* W2    = (const float*)d_in[6];
    const float* b2    = (const float*)d_in[7];
    float* out = (float*)d_out;

    cudaFuncSetAttribute(k_simw, cudaFuncAttributeMaxDynamicSharedMemorySize, SIM_SMEM_SIZE);

    k_init  <<<32, 256>>>();
    k_gemm1 <<<dim3(4, 64), 256>>>(h1, h2, W1, b1);
    k_bnfin <<<4, 256>>>(gamma, beta);
    k_gemm2 <<<256, 256>>>(W2, b2, out, out_size);
    k_pos   <<<512, 256>>>();
    k_simw  <<<2080, 256, SIM_SMEM_SIZE>>>();
    k_finish<<<1024, 256>>>();
    k_out   <<<1, 1>>>(out, out_size);
}

// round 6
// speedup vs baseline: 4.2714x; 1.3095x over previous
#include <cuda_runtime.h>
#include <cuda_bf16.h>
#include <math.h>
#include <stdint.h>

#define B_ROWS 4096
#define D_INF  192
#define D_HID  512
#define D_OUTF 128
#define M2     8192      // 2*B
#define INV_T  2.0f      // 1/TEMPERATURE
#define BN_EPS 1e-5f
#define L2_EPS 1e-12f

// ---------------- scratch (static device globals; no allocation) ------------
__device__ __align__(128) float g_Y[(size_t)M2 * D_HID];     // 16 MB
__device__ __align__(128) float g_Z[(size_t)M2 * D_OUTF];    // 4 MB
__device__ __align__(128) __nv_bfloat16 g_Zh[(size_t)M2 * D_OUTF]; // 2 MB
__device__ float g_colsum[2][D_HID];
__device__ float g_colsq[2][D_HID];
__device__ float g_scale[2][D_HID];
__device__ float g_shift[2][D_HID];
__device__ float g_sumexp[M2];
__device__ float g_pos[B_ROWS];
__device__ float g_loss[1];

// ---------------- helpers ----------------------------------------------------
__device__ __forceinline__ void mma16816(float* c, const uint32_t* a, const uint32_t* b) {
    asm volatile(
        "mma.sync.aligned.m16n8k16.row.col.f32.bf16.bf16.f32 "
        "{%0,%1,%2,%3}, {%4,%5,%6,%7}, {%8,%9}, {%0,%1,%2,%3};"
        : "+f"(c[0]), "+f"(c[1]), "+f"(c[2]), "+f"(c[3])
        : "r"(a[0]), "r"(a[1]), "r"(a[2]), "r"(a[3]), "r"(b[0]), "r"(b[1]));
}
// split fp32 pair into bf16x2 hi + bf16x2 lo (x = hi + lo, err ~2^-18)
__device__ __forceinline__ void split2(float f0, float f1, uint32_t& hi, uint32_t& lo) {
    __nv_bfloat162 h = __floats2bfloat162_rn(f0, f1);
    __nv_bfloat162 l = __floats2bfloat162_rn(f0 - __bfloat162float(h.x),
                                             f1 - __bfloat162float(h.y));
    hi = *reinterpret_cast<uint32_t*>(&h);
    lo = *reinterpret_cast<uint32_t*>(&l);
}

// smem tile geometry for the split-bf16 GEMMs (pitch 36 words = 72 bf16)
#define PW  36
#define SAW (64 * PW)     // A tile: 64 rows
#define SBW (128 * PW)    // B tile: 128 rows
#define GSM_BYTES (((2 * SAW + 2 * SBW) * 4) + 2048)   // 57344

// ---------------- init ------------------------------------------------------
__global__ void k_init() {
    int i = blockIdx.x * blockDim.x + threadIdx.x;
    if (i < M2) g_sumexp[i] = 0.f;
    if (i < 2 * D_HID) {
        g_colsum[i >> 9][i & 511] = 0.f;
        g_colsq [i >> 9][i & 511] = 0.f;
    }
    if (i == 0) g_loss[0] = 0.f;
}

// ---------------- GEMM1 (tensor, split-bf16): Y = A @ W1^T + b1 + BN partials
// BM=64, BN=128, K=192 in 3 chunks of 64. 8 warps (2m x 4n), warp tile 32x32.
__global__ __launch_bounds__(256) void k_gemm1t(const float* __restrict__ h1,
                                                const float* __restrict__ h2,
                                                const float* __restrict__ W1,
                                                const float* __restrict__ b1) {
    extern __shared__ __align__(16) uint32_t sw[];
    uint32_t* sAhi = sw;
    uint32_t* sAlo = sw + SAW;
    uint32_t* sBhi = sw + 2 * SAW;
    uint32_t* sBlo = sw + 2 * SAW + SBW;
    float* colS = (float*)(sw + 2 * SAW + 2 * SBW);
    float* colQ = colS + 128;

    const int t = threadIdx.x;
    const int wid = t >> 5, lane = t & 31;
    const int gr = lane >> 2, qq = lane & 3;
    const int warp_m = wid >> 2, warp_n = wid & 3;
    const int n0 = blockIdx.x * 128;
    const int m0 = blockIdx.y * 64;
    const int half = (m0 >= B_ROWS);
    const float* A = half ? (h2 + (size_t)(m0 - B_ROWS) * D_INF)
                          : (h1 + (size_t)m0 * D_INF);

    if (t < 128) { colS[t] = 0.f; colQ[t] = 0.f; }

    float acc[2][4][4];
#pragma unroll
    for (int mi = 0; mi < 2; mi++)
#pragma unroll
        for (int ni = 0; ni < 4; ni++)
#pragma unroll
            for (int r = 0; r < 4; r++) acc[mi][ni][r] = 0.f;

    const int arow = t >> 2, acq = (t & 3) * 16;
    const int brow = t >> 1, bcq = (t & 1) * 32;

    for (int kb = 0; kb < D_INF; kb += 64) {
        {
            const float* pa = A + (size_t)arow * D_INF + kb + acq;
#pragma unroll
            for (int j = 0; j < 4; j++) {
                float4 v = *(const float4*)(pa + j * 4);
                uint32_t h0, l0, h1, l1;
                split2(v.x, v.y, h0, l0);
                split2(v.z, v.w, h1, l1);
                int w = arow * PW + (acq >> 1) + j * 2;
                sAhi[w] = h0; sAhi[w + 1] = h1;
                sAlo[w] = l0; sAlo[w + 1] = l1;
            }
            const float* pb = W1 + (size_t)(n0 + brow) * D_INF + kb + bcq;
#pragma unroll
            for (int j = 0; j < 8; j++) {
                float4 v = *(const float4*)(pb + j * 4);
                uint32_t h0, l0, h1, l1;
                split2(v.x, v.y, h0, l0);
                split2(v.z, v.w, h1, l1);
                int w = brow * PW + (bcq >> 1) + j * 2;
                sBhi[w] = h0; sBhi[w + 1] = h1;
                sBlo[w] = l0; sBlo[w + 1] = l1;
            }
        }
        __syncthreads();
#pragma unroll
        for (int ks = 0; ks < 4; ks++) {
            int kw = ks * 8 + qq;
            uint32_t ah[2][4], al[2][4], bh[4][2], bl[4][2];
#pragma unroll
            for (int mi = 0; mi < 2; mi++) {
                int r0 = warp_m * 32 + mi * 16 + gr;
                ah[mi][0] = sAhi[r0 * PW + kw];       ah[mi][1] = sAhi[(r0 + 8) * PW + kw];
                ah[mi][2] = sAhi[r0 * PW + kw + 4];   ah[mi][3] = sAhi[(r0 + 8) * PW + kw + 4];
                al[mi][0] = sAlo[r0 * PW + kw];       al[mi][1] = sAlo[(r0 + 8) * PW + kw];
                al[mi][2] = sAlo[r0 * PW + kw + 4];   al[mi][3] = sAlo[(r0 + 8) * PW + kw + 4];
            }
#pragma unroll
            for (int ni = 0; ni < 4; ni++) {
                int nr = warp_n * 32 + ni * 8 + gr;
                bh[ni][0] = sBhi[nr * PW + kw];  bh[ni][1] = sBhi[nr * PW + kw + 4];
                bl[ni][0] = sBlo[nr * PW + kw];  bl[ni][1] = sBlo[nr * PW + kw + 4];
            }
#pragma unroll
            for (int mi = 0; mi < 2; mi++)
#pragma unroll
                for (int ni = 0; ni < 4; ni++) {
                    mma16816(acc[mi][ni], ah[mi], bh[ni]);
                    mma16816(acc[mi][ni], ah[mi], bl[ni]);
                    mma16816(acc[mi][ni], al[mi], bh[ni]);
                }
        }
        __syncthreads();
    }

    // epilogue: bias, store Y, per-column sum/sumsq partials
    float ps[4][2], pq[4][2];
#pragma unroll
    for (int ni = 0; ni < 4; ni++) { ps[ni][0]=ps[ni][1]=pq[ni][0]=pq[ni][1]=0.f; }
#pragma unroll
    for (int ni = 0; ni < 4; ni++) {
        int col = warp_n * 32 + ni * 8 + qq * 2;
        float2 bb = *(const float2*)&b1[n0 + col];
#pragma unroll
        for (int mi = 0; mi < 2; mi++) {
            int r = warp_m * 32 + mi * 16 + gr;
            float y0 = acc[mi][ni][0] + bb.x;
            float y1 = acc[mi][ni][1] + bb.y;
            float y2 = acc[mi][ni][2] + bb.x;
            float y3 = acc[mi][ni][3] + bb.y;
            float2 p0 = {y0, y1}, p1 = {y2, y3};
            *(float2*)&g_Y[(size_t)(m0 + r)     * D_HID + n0 + col] = p0;
            *(float2*)&g_Y[(size_t)(m0 + r + 8) * D_HID + n0 + col] = p1;
            ps[ni][0] += y0 + y2;              ps[ni][1] += y1 + y3;
            pq[ni][0] += y0 * y0 + y2 * y2;    pq[ni][1] += y1 * y1 + y3 * y3;
        }
    }
#pragma unroll
    for (int ni = 0; ni < 4; ni++)
#pragma unroll
        for (int c2 = 0; c2 < 2; c2++) {
            float s = ps[ni][c2], q = pq[ni][c2];
            s += __shfl_xor_sync(~0u, s, 4);  q += __shfl_xor_sync(~0u, q, 4);
            s += __shfl_xor_sync(~0u, s, 8);  q += __shfl_xor_sync(~0u, q, 8);
            s += __shfl_xor_sync(~0u, s, 16); q += __shfl_xor_sync(~0u, q, 16);
            ps[ni][c2] = s; pq[ni][c2] = q;
        }
    if (gr == 0) {
#pragma unroll
        for (int ni = 0; ni < 4; ni++) {
            int col = warp_n * 32 + ni * 8 + qq * 2;
            atomicAdd(&colS[col],     ps[ni][0]);
            atomicAdd(&colS[col + 1], ps[ni][1]);
            atomicAdd(&colQ[col],     pq[ni][0]);
            atomicAdd(&colQ[col + 1], pq[ni][1]);
        }
    }
    __syncthreads();
    if (t < 128) {
        atomicAdd(&g_colsum[half][n0 + t], colS[t]);
        atomicAdd(&g_colsq [half][n0 + t], colQ[t]);
    }
}

// ---------------- finalize BN scale/shift ------------------------------------
__global__ void k_bnfin(const float* __restrict__ gamma,
                        const float* __restrict__ beta) {
    int i = blockIdx.x * blockDim.x + threadIdx.x;
    if (i >= 2 * D_HID) return;
    int half = i >> 9, c = i & 511;
    float mean = g_colsum[half][c] * (1.f / B_ROWS);
    float var  = g_colsq [half][c] * (1.f / B_ROWS) - mean * mean;
    float sc   = gamma[c] * rsqrtf(var + BN_EPS);
    g_scale[half][c] = sc;
    g_shift[half][c] = beta[c] - mean * sc;
}

// ---------------- GEMM2 (tensor, split-bf16): Z = relu(BN(Y)) @ W2^T + b2 ----
// BM=64, BN=128(=D_OUT), K=512 in 8 chunks of 64. Fused bias+L2-norm+emit.
__global__ __launch_bounds__(256) void k_gemm2t(const float* __restrict__ W2,
                                                const float* __restrict__ b2,
                                                float* __restrict__ out,
                                                int out_size) {
    extern __shared__ __align__(16) uint32_t sw[];
    uint32_t* sAhi = sw;
    uint32_t* sAlo = sw + SAW;
    uint32_t* sBhi = sw + 2 * SAW;
    uint32_t* sBlo = sw + 2 * SAW + SBW;
    float* red  = (float*)(sw + 2 * SAW + 2 * SBW);   // [64][4]
    float* sInv = red + 256;

    const int t = threadIdx.x;
    const int wid = t >> 5, lane = t & 31;
    const int gr = lane >> 2, qq = lane & 3;
    const int warp_m = wid >> 2, warp_n = wid & 3;
    const int m0 = blockIdx.x * 64;
    const int half = (m0 >= B_ROWS);
    const float* __restrict__ sc = g_scale[half];
    const float* __restrict__ sh = g_shift[half];

    float acc[2][4][4];
#pragma unroll
    for (int mi = 0; mi < 2; mi++)
#pragma unroll
        for (int ni = 0; ni < 4; ni++)
#pragma unroll
            for (int r = 0; r < 4; r++) acc[mi][ni][r] = 0.f;

    const int arow = t >> 2, acq = (t & 3) * 16;
    const int brow = t >> 1, bcq = (t & 1) * 32;

    for (int kb = 0; kb < D_HID; kb += 64) {
        {
            const float* pa = g_Y + (size_t)(m0 + arow) * D_HID + kb + acq;
#pragma unroll
            for (int j = 0; j < 4; j++) {
                float4 v = *(const float4*)(pa + j * 4);
                int k = kb + acq + j * 4;
                float f0 = fmaxf(fmaf(v.x, sc[k],     sh[k]),     0.f);
                float f1 = fmaxf(fmaf(v.y, sc[k + 1], sh[k + 1]), 0.f);
                float f2 = fmaxf(fmaf(v.z, sc[k + 2], sh[k + 2]), 0.f);
                float f3 = fmaxf(fmaf(v.w, sc[k + 3], sh[k + 3]), 0.f);
                uint32_t h0, l0, h1, l1;
                split2(f0, f1, h0, l0);
                split2(f2, f3, h1, l1);
                int w = arow * PW + (acq >> 1) + j * 2;
                sAhi[w] = h0; sAhi[w + 1] = h1;
                sAlo[w] = l0; sAlo[w + 1] = l1;
            }
            const float* pb = W2 + (size_t)brow * D_HID + kb + bcq;
#pragma unroll
            for (int j = 0; j < 8; j++) {
                float4 v = *(const float4*)(pb + j * 4);
                uint32_t h0, l0, h1, l1;
                split2(v.x, v.y, h0, l0);
                split2(v.z, v.w, h1, l1);
                int w = brow * PW + (bcq >> 1) + j * 2;
                sBhi[w] = h0; sBhi[w + 1] = h1;
                sBlo[w] = l0; sBlo[w + 1] = l1;
            }
        }
        __syncthreads();
#pragma unroll
        for (int ks = 0; ks < 4; ks++) {
            int kw = ks * 8 + qq;
            uint32_t ah[2][4], al[2][4], bh[4][2], bl[4][2];
#pragma unroll
            for (int mi = 0; mi < 2; mi++) {
                int r0 = warp_m * 32 + mi * 16 + gr;
                ah[mi][0] = sAhi[r0 * PW + kw];       ah[mi][1] = sAhi[(r0 + 8) * PW + kw];
                ah[mi][2] = sAhi[r0 * PW + kw + 4];   ah[mi][3] = sAhi[(r0 + 8) * PW + kw + 4];
                al[mi][0] = sAlo[r0 * PW + kw];       al[mi][1] = sAlo[(r0 + 8) * PW + kw];
                al[mi][2] = sAlo[r0 * PW + kw + 4];   al[mi][3] = sAlo[(r0 + 8) * PW + kw + 4];
            }
#pragma unroll
            for (int ni = 0; ni < 4; ni++) {
                int nr = warp_n * 32 + ni * 8 + gr;
                bh[ni][0] = sBhi[nr * PW + kw];  bh[ni][1] = sBhi[nr * PW + kw + 4];
                bl[ni][0] = sBlo[nr * PW + kw];  bl[ni][1] = sBlo[nr * PW + kw + 4];
            }
#pragma unroll
            for (int mi = 0; mi < 2; mi++)
#pragma unroll
                for (int ni = 0; ni < 4; ni++) {
                    mma16816(acc[mi][ni], ah[mi], bh[ni]);
                    mma16816(acc[mi][ni], ah[mi], bl[ni]);
                    mma16816(acc[mi][ni], al[mi], bh[ni]);
                }
        }
        __syncthreads();
    }

    // epilogue: bias, row L2 norms, normalize, emit
    float rp[2][2] = {{0.f, 0.f}, {0.f, 0.f}};
#pragma unroll
    for (int ni = 0; ni < 4; ni++) {
        int col = warp_n * 32 + ni * 8 + qq * 2;
        float2 bb = *(const float2*)&b2[col];
#pragma unroll
        for (int mi = 0; mi < 2; mi++) {
            acc[mi][ni][0] += bb.x; acc[mi][ni][1] += bb.y;
            acc[mi][ni][2] += bb.x; acc[mi][ni][3] += bb.y;
            rp[mi][0] = fmaf(acc[mi][ni][0], acc[mi][ni][0],
                        fmaf(acc[mi][ni][1], acc[mi][ni][1], rp[mi][0]));
            rp[mi][1] = fmaf(acc[mi][ni][2], acc[mi][ni][2],
                        fmaf(acc[mi][ni][3], acc[mi][ni][3], rp[mi][1]));
        }
    }
#pragma unroll
    for (int mi = 0; mi < 2; mi++)
#pragma unroll
        for (int rh = 0; rh < 2; rh++) {
            float s = rp[mi][rh];
            s += __shfl_xor_sync(~0u, s, 1);
            s += __shfl_xor_sync(~0u, s, 2);
            rp[mi][rh] = s;
        }
    if (qq == 0) {
#pragma unroll
        for (int mi = 0; mi < 2; mi++) {
            red[(warp_m * 32 + mi * 16 + gr)     * 4 + warp_n] = rp[mi][0];
            red[(warp_m * 32 + mi * 16 + gr + 8) * 4 + warp_n] = rp[mi][1];
        }
    }
    __syncthreads();
    if (t < 64) {
        float s = red[t * 4] + red[t * 4 + 1] + red[t * 4 + 2] + red[t * 4 + 3];
        sInv[t] = 1.f / fmaxf(sqrtf(s), L2_EPS);
    }
    __syncthreads();
    bool full = (out_size > M2 * D_OUTF);
#pragma unroll
    for (int mi = 0; mi < 2; mi++)
#pragma unroll
        for (int rh = 0; rh < 2; rh++) {
            int r = warp_m * 32 + mi * 16 + gr + rh * 8;
            float inv = sInv[r];
            int m = m0 + r;
#pragma unroll
            for (int ni = 0; ni < 4; ni++) {
                int col = warp_n * 32 + ni * 8 + qq * 2;
                float z0 = acc[mi][ni][rh * 2]     * inv;
                float z1 = acc[mi][ni][rh * 2 + 1] * inv;
                float2 zz = {z0, z1};
                *(float2*)&g_Z[(size_t)m * D_OUTF + col] = zz;
                *(__nv_bfloat162*)&g_Zh[(size_t)m * D_OUTF + col] =
                    __floats2bfloat162_rn(z0, z1);
                if (full) {
                    out[1 + (size_t)m * D_OUTF + col]     = z0;
                    out[1 + (size_t)m * D_OUTF + col + 1] = z1;
                }
            }
        }
}

// ---------------- pos[i] = z1_i . z2_i / T ----------------------------------
__global__ void k_pos() {
    int w    = (blockIdx.x * blockDim.x + threadIdx.x) >> 5;
    int lane = threadIdx.x & 31;
    if (w >= B_ROWS) return;
    float4 a = *(const float4*)(g_Z + (size_t)w * D_OUTF + lane * 4);
    float4 b = *(const float4*)(g_Z + (size_t)(w + B_ROWS) * D_OUTF + lane * 4);
    float d = a.x*b.x + a.y*b.y + a.z*b.z + a.w*b.w;
#pragma unroll
    for (int o = 16; o; o >>= 1) d += __shfl_down_sync(0xffffffffu, d, o);
    if (lane == 0) g_pos[w] = d * INV_T;
}

// ---------------- tensor-core sim via mma.sync (bf16, fp32 accum) -----------
#define SIM_PITCH 136
#define SIM_TILE_BYTES (128 * SIM_PITCH * 2)
#define SIM_SMEM_SIZE (2 * SIM_TILE_BYTES + 2 * 128 * 4)

__device__ __forceinline__ int tri_off(int r) { return r * 64 - ((r * (r - 1)) >> 1); }

__global__ __launch_bounds__(256) void k_simw() {
    extern __shared__ __align__(16) char smem[];
    __nv_bfloat16* sA = (__nv_bfloat16*)smem;
    __nv_bfloat16* sB = (__nv_bfloat16*)(smem + SIM_TILE_BYTES);
    float* srow = (float*)(smem + 2 * SIM_TILE_BYTES);
    float* scol = srow + 128;
    const uint32_t* sAw = (const uint32_t*)sA;
    const uint32_t* sBw = (const uint32_t*)sB;

    const int t = threadIdx.x;
    const int wid = t >> 5, lane = t & 31;
    const int gr = lane >> 2;
    const int qq = lane & 3;
    const int warp_m = wid >> 2;
    const int warp_n = wid & 3;

    int tb = blockIdx.x;
    int bi = (int)(64.5f - sqrtf(64.5f * 64.5f - 2.0f * (float)tb));
    if (bi < 0) bi = 0; if (bi > 63) bi = 63;
    while (tri_off(bi + 1) <= tb) ++bi;
    while (tri_off(bi) > tb) --bi;
    int bj = bi + (tb - tri_off(bi));
    const size_t i0 = (size_t)bi * 128;
    const size_t j0 = (size_t)bj * 128;

    if (t < 128) { srow[t] = 0.f; scol[t] = 0.f; }

#pragma unroll
    for (int it = 0; it < 8; it++) {
        int q   = t + it * 256;
        int row = q >> 4;
        int cb  = q & 15;
        uint4 va = *(const uint4*)(g_Zh + (i0 + row) * D_OUTF + cb * 8);
        uint4 vb = *(const uint4*)(g_Zh + (j0 + row) * D_OUTF + cb * 8);
        *(uint4*)((char*)sA + row * (SIM_PITCH * 2) + cb * 16) = va;
        *(uint4*)((char*)sB + row * (SIM_PITCH * 2) + cb * 16) = vb;
    }
    __syncthreads();

    float c[4][4][4];
#pragma unroll
    for (int mi = 0; mi < 4; mi++)
#pragma unroll
        for (int ni = 0; ni < 4; ni++)
#pragma unroll
            for (int r = 0; r < 4; r++) c[mi][ni][r] = 0.f;

    const int PWS = SIM_PITCH / 2;
#pragma unroll
    for (int ks = 0; ks < 8; ks++) {
        int kw = ks * 8 + qq;
        uint32_t a[4][4], b[4][2];
#pragma unroll
        for (int mi = 0; mi < 4; mi++) {
            int r0 = warp_m * 64 + mi * 16 + gr;
            a[mi][0] = sAw[r0 * PWS + kw];
            a[mi][1] = sAw[(r0 + 8) * PWS + kw];
            a[mi][2] = sAw[r0 * PWS + kw + 4];
            a[mi][3] = sAw[(r0 + 8) * PWS + kw + 4];
        }
#pragma unroll
        for (int ni = 0; ni < 4; ni++) {
            int n0 = warp_n * 32 + ni * 8 + gr;
            b[ni][0] = sBw[n0 * PWS + kw];
            b[ni][1] = sBw[n0 * PWS + kw + 4];
        }
#pragma unroll
        for (int mi = 0; mi < 4; mi++)
#pragma unroll
            for (int ni = 0; ni < 4; ni++)
                mma16816(c[mi][ni], a[mi], b[ni]);
    }

    float rsum[8], csum[8];
#pragma unroll
    for (int i = 0; i < 8; i++) { rsum[i] = 0.f; csum[i] = 0.f; }
#pragma unroll
    for (int mi = 0; mi < 4; mi++)
#pragma unroll
        for (int ni = 0; ni < 4; ni++) {
            float e0 = __expf(c[mi][ni][0] * INV_T);
            float e1 = __expf(c[mi][ni][1] * INV_T);
            float e2 = __expf(c[mi][ni][2] * INV_T);
            float e3 = __expf(c[mi][ni][3] * INV_T);
            rsum[mi * 2 + 0] += e0 + e1;
            rsum[mi * 2 + 1] += e2 + e3;
            csum[ni * 2 + 0] += e0 + e2;
            csum[ni * 2 + 1] += e1 + e3;
        }
#pragma unroll
    for (int i = 0; i < 8; i++) {
        rsum[i] += __shfl_xor_sync(0xffffffffu, rsum[i], 1);
        rsum[i] += __shfl_xor_sync(0xffffffffu, rsum[i], 2);
    }
    if (qq == 0) {
#pragma unroll
        for (int mi = 0; mi < 4; mi++) {
            atomicAdd(&srow[warp_m * 64 + mi * 16 + gr],     rsum[mi * 2 + 0]);
            atomicAdd(&srow[warp_m * 64 + mi * 16 + gr + 8], rsum[mi * 2 + 1]);
        }
    }
#pragma unroll
    for (int i = 0; i < 8; i++) {
        csum[i] += __shfl_xor_sync(0xffffffffu, csum[i], 4);
        csum[i] += __shfl_xor_sync(0xffffffffu, csum[i], 8);
        csum[i] += __shfl_xor_sync(0xffffffffu, csum[i], 16);
    }
    if (gr == 0) {
#pragma unroll
        for (int ni = 0; ni < 4; ni++) {
            atomicAdd(&scol[warp_n * 32 + ni * 8 + qq * 2],     csum[ni * 2 + 0]);
            atomicAdd(&scol[warp_n * 32 + ni * 8 + qq * 2 + 1], csum[ni * 2 + 1]);
        }
    }
    __syncthreads();
    if (t < 128) {
        atomicAdd(&g_sumexp[i0 + t], srow[t]);
        if (bi != bj) atomicAdd(&g_sumexp[j0 + t], scol[t]);
    }
}

// ---------------- finish: loss = mean(lse_i - pos_i) ------------------------
__global__ void k_finish() {
    int w    = (blockIdx.x * blockDim.x + threadIdx.x) >> 5;
    int lane = threadIdx.x & 31;
    if (w >= M2) return;
    const __nv_bfloat16* zr = g_Zh + (size_t)w * D_OUTF + lane * 4;
    float d = 0.f;
#pragma unroll
    for (int j = 0; j < 4; j++) {
        float v = __bfloat162float(zr[j]);
        d = fmaf(v, v, d);
    }
#pragma unroll
    for (int o = 16; o; o >>= 1) d += __shfl_down_sync(0xffffffffu, d, o);
    if (lane == 0) {
        float se  = g_sumexp[w] - __expf(d * INV_T);
        float lse = logf(se);
        float li  = lse - g_pos[w & (B_ROWS - 1)];
        atomicAdd(&g_loss[0], li * (1.f / M2));
    }
}

// ---------------- emit loss --------------------------------------------------
__global__ void k_out(float* __restrict__ out, int out_size) {
    if (out_size > 0) out[0] = g_loss[0];
}

// ---------------- launch -----------------------------------------------------
extern "C" void kernel_launch(void* const* d_in, const int* in_sizes, int n_in,
                              void* d_out, int out_size) {
    const float* h1    = (const float*)d_in[0];
    const float* h2    = (const float*)d_in[1];
    const float* W1    = (const float*)d_in[2];
    const float* b1    = (const float*)d_in[3];
    const float* gamma = (const float*)d_in[4];
    const float* beta  = (const float*)d_in[5];
    const float* W2    = (const float*)d_in[6];
    const float* b2    = (const float*)d_in[7];
    float* out = (float*)d_out;

    cudaFuncSetAttribute(k_gemm1t, cudaFuncAttributeMaxDynamicSharedMemorySize, GSM_BYTES);
    cudaFuncSetAttribute(k_gemm2t, cudaFuncAttributeMaxDynamicSharedMemorySize, GSM_BYTES);
    cudaFuncSetAttribute(k_simw,   cudaFuncAttributeMaxDynamicSharedMemorySize, SIM_SMEM_SIZE);

    k_init   <<<32, 256>>>();
    k_gemm1t <<<dim3(4, 128), 256, GSM_BYTES>>>(h1, h2, W1, b1);
    k_bnfin  <<<4, 256>>>(gamma, beta);
    k_gemm2t <<<128, 256, GSM_BYTES>>>(W2, b2, out, out_size);
    k_pos    <<<512, 256>>>();
    k_simw   <<<2080, 256, SIM_SMEM_SIZE>>>();
    k_finish <<<1024, 256>>>();
    k_out    <<<1, 1>>>(out, out_size);
}